// round 1
// baseline (speedup 1.0000x reference)
#include <cuda_runtime.h>
#include <cstdint>

#define TOK (32*8192)
#define NBATCH 8192
#define HD 128

// ---------------- scratch (no allocations allowed) ----------------
__device__ float g_h[(size_t)TOK*HD];     // hidden state, 134MB
__device__ float g_G[(size_t)TOK*HD];     // pre-BN h_new, 134MB
__device__ float g_part[2048*256];        // per-CTA channel sum/sumsq partials
__device__ float g_sc[128];
__device__ float g_sh[128];

// ---------------- helpers ----------------
__device__ __forceinline__ float tf32r(float x) {
    uint32_t u;
    asm("cvt.rna.tf32.f32 %0, %1;" : "=r"(u) : "f"(x));
    return __uint_as_float(u);
}
__device__ __forceinline__ uint32_t fb(float x) { return __float_as_uint(x); }

__device__ __forceinline__ void mma8(float c[4], const uint32_t a[4], const uint32_t b[2]) {
    asm volatile(
        "mma.sync.aligned.m16n8k8.row.col.f32.tf32.tf32.f32 "
        "{%0,%1,%2,%3},{%4,%5,%6,%7},{%8,%9},{%0,%1,%2,%3};\n"
        : "+f"(c[0]), "+f"(c[1]), "+f"(c[2]), "+f"(c[3])
        : "r"(a[0]), "r"(a[1]), "r"(a[2]), "r"(a[3]), "r"(b[0]), "r"(b[1]));
}

// ---------------- embedding: h = x @ emb_w + emb_b ----------------
__global__ void emb_kernel(const float* __restrict__ x,
                           const float* __restrict__ ew,
                           const float* __restrict__ eb) {
    __shared__ float w0[128], w1[128], bb[128];
    if (threadIdx.x < 128) {
        w0[threadIdx.x] = ew[threadIdx.x];
        w1[threadIdx.x] = ew[128 + threadIdx.x];
        bb[threadIdx.x] = eb[threadIdx.x];
    }
    __syncthreads();
    size_t idx = (size_t)blockIdx.x * 256 + threadIdx.x;   // float4 index, total TOK*32
    size_t t = idx >> 5;
    int c = (int)(idx & 31) << 2;
    float2 xv = *(const float2*)(x + t * 2);
    float4 o;
    o.x = xv.x * w0[c]   + xv.y * w1[c]   + bb[c];
    o.y = xv.x * w0[c+1] + xv.y * w1[c+1] + bb[c+1];
    o.z = xv.x * w0[c+2] + xv.y * w1[c+2] + bb[c+2];
    o.w = xv.x * w0[c+3] + xv.y * w1[c+3] + bb[c+3];
    *(float4*)(g_h + t * HD + c) = o;
}

// ---------------- graph-conv GEMM with fused ring-roll + BN partials ----------------
// CTA: 128 token rows (+2 halo in smem). 512 threads = 16 warps.
// Warps wn<2 : P = A @ lin_w   (A rows r)
// Warps wn>=2: R = A' @ nb_w   (A'[r] = A[r-1]+A[r+1], built on-the-fly from halo tile)
// Epilogue combines P+R+biases, masks, writes g_G, emits per-channel partial stats.
#define AS_ELEMS (130*132)
#define WS_ELEMS (128*264)
#define GCONV_SMEM ((AS_ELEMS + WS_ELEMS + 256) * 4)

__global__ __launch_bounds__(512, 1) void gconv_kernel(
    const float* __restrict__ lw, const float* __restrict__ nw,
    const float* __restrict__ lb, const float* __restrict__ nbb,
    const float* __restrict__ mask)
{
    extern __shared__ float sm[];
    float* As   = sm;                     // [130][132], logical row r at smem row r+1
    float* Ws   = sm + AS_ELEMS;          // [128][264]: cols 0-127 lin, 128-255 nb
    float* ssum = Ws + WS_ELEMS;          // [128]
    float* ssq  = ssum + 128;             // [128]

    const int tid = threadIdx.x;
    const int bid = blockIdx.x;
    const int b = bid >> 6;               // 64 CTAs per batch
    const int n_base = (bid & 63) << 7;   // *128
    const size_t tok0 = (size_t)b * NBATCH + n_base;

    if (tid < 128) { ssum[tid] = 0.f; ssq[tid] = 0.f; }

    // load A tile with halo (wrap within batch; NBATCH is pow2)
    for (int idx = tid; idx < 130 * 32; idx += 512) {
        int r = idx >> 5, c4 = (idx & 31) << 2;
        int n = (n_base + r - 1) & (NBATCH - 1);
        const float4 v = *(const float4*)(g_h + ((size_t)b * NBATCH + n) * HD + c4);
        float* d = As + r * 132 + c4;
        d[0] = tf32r(v.x); d[1] = tf32r(v.y); d[2] = tf32r(v.z); d[3] = tf32r(v.w);
    }
    // load both weight matrices
    for (int idx = tid; idx < 128 * 32; idx += 512) {
        int k = idx >> 5, c4 = (idx & 31) << 2;
        float4 v = *(const float4*)(lw + k * HD + c4);
        float4 u = *(const float4*)(nw + k * HD + c4);
        float* d = Ws + k * 264 + c4;
        d[0] = tf32r(v.x); d[1] = tf32r(v.y); d[2] = tf32r(v.z); d[3] = tf32r(v.w);
        float* e = d + 128;
        e[0] = tf32r(u.x); e[1] = tf32r(u.y); e[2] = tf32r(u.z); e[3] = tf32r(u.w);
    }
    __syncthreads();

    const int w = tid >> 5, lane = tid & 31;
    const int g = lane >> 2, t4 = lane & 3;
    const int wm = w & 3, wn = w >> 2;
    const bool isR = (wn >= 2);
    const int rbase = wm * 32;
    const int cbase = wn * 64;            // column in Ws (0..255)

    float acc[2][8][4];
    #pragma unroll
    for (int i = 0; i < 2; i++)
        #pragma unroll
        for (int j = 0; j < 8; j++)
            #pragma unroll
            for (int q = 0; q < 4; q++) acc[i][j][q] = 0.f;

    for (int k0 = 0; k0 < 128; k0 += 8) {
        uint32_t afr[2][4];
        #pragma unroll
        for (int mt = 0; mt < 2; mt++) {
            int r0 = rbase + mt * 16 + g;
            if (!isR) {
                const float* p = As + (r0 + 1) * 132 + k0 + t4;
                afr[mt][0] = fb(p[0]);
                afr[mt][1] = fb(p[8 * 132]);
                afr[mt][2] = fb(p[4]);
                afr[mt][3] = fb(p[8 * 132 + 4]);
            } else {
                const float* lo = As + r0 * 132 + k0 + t4;        // logical r-1
                const float* hi = As + (r0 + 2) * 132 + k0 + t4;  // logical r+1
                afr[mt][0] = fb(tf32r(lo[0] + hi[0]));
                afr[mt][1] = fb(tf32r(lo[8 * 132] + hi[8 * 132]));
                afr[mt][2] = fb(tf32r(lo[4] + hi[4]));
                afr[mt][3] = fb(tf32r(lo[8 * 132 + 4] + hi[8 * 132 + 4]));
            }
        }
        uint32_t bfr[8][2];
        #pragma unroll
        for (int nt = 0; nt < 8; nt++) {
            const float* p = Ws + (k0 + t4) * 264 + cbase + nt * 8 + g;
            bfr[nt][0] = fb(p[0]);
            bfr[nt][1] = fb(p[4 * 264]);
        }
        #pragma unroll
        for (int mt = 0; mt < 2; mt++)
            #pragma unroll
            for (int nt = 0; nt < 8; nt++)
                mma8(acc[mt][nt], afr[mt], bfr[nt]);
    }

    __syncthreads();                // all A reads done
    float* S = As;                  // reuse: [128][132]

    if (isR) {
        #pragma unroll
        for (int mt = 0; mt < 2; mt++)
            #pragma unroll
            for (int nt = 0; nt < 8; nt++) {
                int r = rbase + mt * 16 + g;
                int c = (cbase - 128) + nt * 8 + t4 * 2;
                S[r * 132 + c]           = acc[mt][nt][0];
                S[r * 132 + c + 1]       = acc[mt][nt][1];
                S[(r + 8) * 132 + c]     = acc[mt][nt][2];
                S[(r + 8) * 132 + c + 1] = acc[mt][nt][3];
            }
    }
    __syncthreads();
    if (!isR) {
        #pragma unroll
        for (int mt = 0; mt < 2; mt++) {
            int r = rbase + mt * 16 + g;
            float m0 = mask[tok0 + r];
            float m1 = mask[tok0 + r + 8];
            #pragma unroll
            for (int nt = 0; nt < 8; nt++) {
                int c = cbase + nt * 8 + t4 * 2;
                float bia0 = lb[c] + nbb[c];
                float bia1 = lb[c + 1] + nbb[c + 1];
                S[r * 132 + c]           = (acc[mt][nt][0] + S[r * 132 + c]           + bia0) * m0;
                S[r * 132 + c + 1]       = (acc[mt][nt][1] + S[r * 132 + c + 1]       + bia1) * m0;
                S[(r + 8) * 132 + c]     = (acc[mt][nt][2] + S[(r + 8) * 132 + c]     + bia0) * m1;
                S[(r + 8) * 132 + c + 1] = (acc[mt][nt][3] + S[(r + 8) * 132 + c + 1] + bia1) * m1;
            }
        }
    }
    __syncthreads();

    // per-channel partial stats over this tile's 128 rows
    {
        int c = tid & 127, seg = tid >> 7;
        float s = 0.f, q = 0.f;
        #pragma unroll 8
        for (int r = seg * 32; r < seg * 32 + 32; r++) {
            float v = S[r * 132 + c];
            s += v; q += v * v;
        }
        atomicAdd(&ssum[c], s);
        atomicAdd(&ssq[c], q);
    }
    // store pre-BN tile
    for (int idx = tid; idx < 128 * 32; idx += 512) {
        int r = idx >> 5, c4 = (idx & 31) << 2;
        float4 v = *(const float4*)(S + r * 132 + c4);
        *(float4*)(g_G + (tok0 + r) * HD + c4) = v;
    }
    __syncthreads();
    if (tid < 256) g_part[bid * 256 + tid] = (tid < 128) ? ssum[tid] : ssq[tid - 128];
}

// ---------------- BN reduce: 2048 partials -> scale/shift per channel ----------------
__global__ void bnreduce_kernel(const float* __restrict__ gam, const float* __restrict__ bet) {
    __shared__ float rs[256], rq[256];
    int c = blockIdx.x, tid = threadIdx.x;   // grid 128, block 256
    float s = 0.f, q = 0.f;
    #pragma unroll
    for (int i = 0; i < 8; i++) {
        int cta = tid * 8 + i;
        s += g_part[cta * 256 + c];
        q += g_part[cta * 256 + 128 + c];
    }
    rs[tid] = s; rq[tid] = q;
    __syncthreads();
    for (int o = 128; o > 0; o >>= 1) {
        if (tid < o) { rs[tid] += rs[tid + o]; rq[tid] += rq[tid + o]; }
        __syncthreads();
    }
    if (tid == 0) {
        float inv = 1.f / (float)TOK;
        float mean = rs[0] * inv;
        float var = rq[0] * inv - mean * mean;
        float sc = gam[c] * rsqrtf(var + 1e-5f);
        g_sc[c] = sc;
        g_sh[c] = bet[c] - mean * sc;
    }
}

// ---------------- BN apply + ReLU + residual: h += relu(G*sc + sh) ----------------
__global__ void bnapply_kernel() {
    __shared__ float sc[128], sh[128];
    if (threadIdx.x < 128) { sc[threadIdx.x] = g_sc[threadIdx.x]; sh[threadIdx.x] = g_sh[threadIdx.x]; }
    __syncthreads();
    size_t idx = (size_t)blockIdx.x * 256 + threadIdx.x;   // float4 index
    int c = (int)(idx & 31) << 2;
    float4 gv = *(const float4*)(g_G + idx * 4);
    float4 hv = *(const float4*)(g_h + idx * 4);
    hv.x += fmaxf(0.f, gv.x * sc[c]     + sh[c]);
    hv.y += fmaxf(0.f, gv.y * sc[c + 1] + sh[c + 1]);
    hv.z += fmaxf(0.f, gv.z * sc[c + 2] + sh[c + 2]);
    hv.w += fmaxf(0.f, gv.w * sc[c + 3] + sh[c + 3]);
    *(float4*)(g_h + idx * 4) = hv;
}

// ---------------- output head: out = relu(h@W1+b1)@W2 + b2, masked ----------------
#define AS2_ELEMS (128*132)
#define W1S_ELEMS (128*72)
#define OUT_SMEM ((AS2_ELEMS + W1S_ELEMS + 128 + 64) * 4)

__global__ __launch_bounds__(256, 1) void out_kernel(
    const float* __restrict__ w1, const float* __restrict__ b1,
    const float* __restrict__ w2, const float* __restrict__ b2,
    const float* __restrict__ mask, float* __restrict__ out)
{
    extern __shared__ float sm[];
    float* As  = sm;                 // [128][132]
    float* W1s = As + AS2_ELEMS;     // [128][72]
    float* W2s = W1s + W1S_ELEMS;    // [64][2]
    float* B1s = W2s + 128;          // [64]
    const int tid = threadIdx.x, bid = blockIdx.x;
    const size_t tok0 = (size_t)bid * 128;

    for (int idx = tid; idx < 128 * 32; idx += 256) {
        int r = idx >> 5, c4 = (idx & 31) << 2;
        float4 v = *(const float4*)(g_h + (tok0 + r) * HD + c4);
        float* d = As + r * 132 + c4;
        d[0] = tf32r(v.x); d[1] = tf32r(v.y); d[2] = tf32r(v.z); d[3] = tf32r(v.w);
    }
    for (int idx = tid; idx < 128 * 16; idx += 256) {
        int k = idx >> 4, c4 = (idx & 15) << 2;
        float4 v = *(const float4*)(w1 + k * 64 + c4);
        float* d = W1s + k * 72 + c4;
        d[0] = tf32r(v.x); d[1] = tf32r(v.y); d[2] = tf32r(v.z); d[3] = tf32r(v.w);
    }
    if (tid < 128) W2s[tid] = w2[tid];
    if (tid < 64)  B1s[tid] = b1[tid];
    __syncthreads();

    const int w = tid >> 5, lane = tid & 31, g = lane >> 2, t4 = lane & 3;
    const int wm = w & 3, wn = w >> 2;   // 4x2 warp grid over 128x64
    const int rbase = wm * 32, cb = wn * 32;

    float acc[2][4][4];
    #pragma unroll
    for (int i = 0; i < 2; i++)
        #pragma unroll
        for (int j = 0; j < 4; j++)
            #pragma unroll
            for (int q = 0; q < 4; q++) acc[i][j][q] = 0.f;

    for (int k0 = 0; k0 < 128; k0 += 8) {
        uint32_t afr[2][4];
        #pragma unroll
        for (int mt = 0; mt < 2; mt++) {
            const float* p = As + (rbase + mt * 16 + g) * 132 + k0 + t4;
            afr[mt][0] = fb(p[0]);
            afr[mt][1] = fb(p[8 * 132]);
            afr[mt][2] = fb(p[4]);
            afr[mt][3] = fb(p[8 * 132 + 4]);
        }
        uint32_t bfr[4][2];
        #pragma unroll
        for (int nt = 0; nt < 4; nt++) {
            const float* p = W1s + (k0 + t4) * 72 + cb + nt * 8 + g;
            bfr[nt][0] = fb(p[0]);
            bfr[nt][1] = fb(p[4 * 72]);
        }
        #pragma unroll
        for (int mt = 0; mt < 2; mt++)
            #pragma unroll
            for (int nt = 0; nt < 4; nt++)
                mma8(acc[mt][nt], afr[mt], bfr[nt]);
    }
    __syncthreads();

    float* S = As;   // reuse, stride 72
    #pragma unroll
    for (int mt = 0; mt < 2; mt++)
        #pragma unroll
        for (int nt = 0; nt < 4; nt++) {
            int r = rbase + mt * 16 + g;
            int c = cb + nt * 8 + t4 * 2;
            S[r * 72 + c]           = fmaxf(0.f, acc[mt][nt][0] + B1s[c]);
            S[r * 72 + c + 1]       = fmaxf(0.f, acc[mt][nt][1] + B1s[c + 1]);
            S[(r + 8) * 72 + c]     = fmaxf(0.f, acc[mt][nt][2] + B1s[c]);
            S[(r + 8) * 72 + c + 1] = fmaxf(0.f, acc[mt][nt][3] + B1s[c + 1]);
        }
    __syncthreads();

    {
        int r = tid >> 1, o = tid & 1;
        float s = 0.f;
        #pragma unroll
        for (int j = 0; j < 64; j++) s += S[r * 72 + j] * W2s[j * 2 + o];
        out[(tok0 + r) * 2 + o] = (s + b2[o]) * mask[tok0 + r];
    }
}

// ---------------- launch ----------------
extern "C" void kernel_launch(void* const* d_in, const int* in_sizes, int n_in,
                              void* d_out, int out_size) {
    const float* x     = (const float*)d_in[0];
    const float* mask  = (const float*)d_in[1];
    const float* emb_w = (const float*)d_in[2];
    const float* emb_b = (const float*)d_in[3];
    const float* lin_w = (const float*)d_in[4];
    const float* lin_b = (const float*)d_in[5];
    const float* nb_w  = (const float*)d_in[6];
    const float* nb_b  = (const float*)d_in[7];
    const float* bn_g  = (const float*)d_in[8];
    const float* bn_b  = (const float*)d_in[9];
    const float* o1w   = (const float*)d_in[10];
    const float* o1b   = (const float*)d_in[11];
    const float* o2w   = (const float*)d_in[12];
    const float* o2b   = (const float*)d_in[13];
    float* out = (float*)d_out;

    cudaFuncSetAttribute(gconv_kernel, cudaFuncAttributeMaxDynamicSharedMemorySize, GCONV_SMEM);
    cudaFuncSetAttribute(out_kernel,   cudaFuncAttributeMaxDynamicSharedMemorySize, OUT_SMEM);

    emb_kernel<<<32768, 256>>>(x, emb_w, emb_b);
    for (int l = 0; l < 3; l++) {
        gconv_kernel<<<2048, 512, GCONV_SMEM>>>(lin_w + l * 128 * 128, nb_w + l * 128 * 128,
                                                lin_b + l * 128, nb_b + l * 128, mask);
        bnreduce_kernel<<<128, 256>>>(bn_g + l * 128, bn_b + l * 128);
        bnapply_kernel<<<32768, 256>>>();
    }
    out_kernel<<<2048, 256, OUT_SMEM>>>(o1w, o1b, o2w, o2b, mask, out);
}

// round 2
// speedup vs baseline: 1.0013x; 1.0013x over previous
#include <cuda_runtime.h>
#include <cstdint>

#define TOK (32*8192)
#define NBATCH 8192
#define HD 128

// ---------------- scratch (no allocations allowed) ----------------
__device__ float g_h[(size_t)TOK*HD];     // hidden state, 134MB
__device__ float g_G[(size_t)TOK*HD];     // pre-BN h_new, 134MB
__device__ float g_part[2048*256];        // per-CTA channel sum/sumsq partials
__device__ float g_sc[128];
__device__ float g_sh[128];

// ---------------- helpers ----------------
__device__ __forceinline__ float tf32r(float x) {
    uint32_t u;
    asm("cvt.rna.tf32.f32 %0, %1;" : "=r"(u) : "f"(x));
    return __uint_as_float(u);
}
__device__ __forceinline__ uint32_t fb(float x) { return __float_as_uint(x); }

__device__ __forceinline__ void mma8(float c[4], const uint32_t a[4], const uint32_t b[2]) {
    asm volatile(
        "mma.sync.aligned.m16n8k8.row.col.f32.tf32.tf32.f32 "
        "{%0,%1,%2,%3},{%4,%5,%6,%7},{%8,%9},{%0,%1,%2,%3};\n"
        : "+f"(c[0]), "+f"(c[1]), "+f"(c[2]), "+f"(c[3])
        : "r"(a[0]), "r"(a[1]), "r"(a[2]), "r"(a[3]), "r"(b[0]), "r"(b[1]));
}

// ---------------- embedding: h = x @ emb_w + emb_b ----------------
__global__ void emb_kernel(const float* __restrict__ x,
                           const float* __restrict__ ew,
                           const float* __restrict__ eb) {
    __shared__ float w0[128], w1[128], bb[128];
    if (threadIdx.x < 128) {
        w0[threadIdx.x] = ew[threadIdx.x];
        w1[threadIdx.x] = ew[128 + threadIdx.x];
        bb[threadIdx.x] = eb[threadIdx.x];
    }
    __syncthreads();
    size_t idx = (size_t)blockIdx.x * 256 + threadIdx.x;   // float4 index, total TOK*32
    size_t t = idx >> 5;
    int c = (int)(idx & 31) << 2;
    float2 xv = *(const float2*)(x + t * 2);
    float4 o;
    o.x = xv.x * w0[c]   + xv.y * w1[c]   + bb[c];
    o.y = xv.x * w0[c+1] + xv.y * w1[c+1] + bb[c+1];
    o.z = xv.x * w0[c+2] + xv.y * w1[c+2] + bb[c+2];
    o.w = xv.x * w0[c+3] + xv.y * w1[c+3] + bb[c+3];
    *(float4*)(g_h + t * HD + c) = o;
}

// ---------------- graph-conv GEMM with fused ring-roll + BN partials ----------------
// CTA: 128 token rows (+2 halo in smem). 512 threads = 16 warps.
// Warps wn<2 : P = A @ lin_w   (A rows r)
// Warps wn>=2: R = A' @ nb_w   (A'[r] = A[r-1]+A[r+1], built on-the-fly from halo tile)
// Epilogue combines P+R+biases, masks, writes g_G, emits per-channel partial stats.
#define AS_ELEMS (130*132)
#define WS_ELEMS (128*264)
#define GCONV_SMEM ((AS_ELEMS + WS_ELEMS + 256) * 4)

__global__ __launch_bounds__(512, 1) void gconv_kernel(
    const float* __restrict__ lw, const float* __restrict__ nw,
    const float* __restrict__ lb, const float* __restrict__ nbb,
    const float* __restrict__ mask)
{
    extern __shared__ float sm[];
    float* As   = sm;                     // [130][132], logical row r at smem row r+1
    float* Ws   = sm + AS_ELEMS;          // [128][264]: cols 0-127 lin, 128-255 nb
    float* ssum = Ws + WS_ELEMS;          // [128]
    float* ssq  = ssum + 128;             // [128]

    const int tid = threadIdx.x;
    const int bid = blockIdx.x;
    const int b = bid >> 6;               // 64 CTAs per batch
    const int n_base = (bid & 63) << 7;   // *128
    const size_t tok0 = (size_t)b * NBATCH + n_base;

    if (tid < 128) { ssum[tid] = 0.f; ssq[tid] = 0.f; }

    // load A tile with halo (wrap within batch; NBATCH is pow2)
    for (int idx = tid; idx < 130 * 32; idx += 512) {
        int r = idx >> 5, c4 = (idx & 31) << 2;
        int n = (n_base + r - 1) & (NBATCH - 1);
        const float4 v = *(const float4*)(g_h + ((size_t)b * NBATCH + n) * HD + c4);
        float* d = As + r * 132 + c4;
        d[0] = tf32r(v.x); d[1] = tf32r(v.y); d[2] = tf32r(v.z); d[3] = tf32r(v.w);
    }
    // load both weight matrices
    for (int idx = tid; idx < 128 * 32; idx += 512) {
        int k = idx >> 5, c4 = (idx & 31) << 2;
        float4 v = *(const float4*)(lw + k * HD + c4);
        float4 u = *(const float4*)(nw + k * HD + c4);
        float* d = Ws + k * 264 + c4;
        d[0] = tf32r(v.x); d[1] = tf32r(v.y); d[2] = tf32r(v.z); d[3] = tf32r(v.w);
        float* e = d + 128;
        e[0] = tf32r(u.x); e[1] = tf32r(u.y); e[2] = tf32r(u.z); e[3] = tf32r(u.w);
    }
    __syncthreads();

    const int w = tid >> 5, lane = tid & 31;
    const int g = lane >> 2, t4 = lane & 3;
    const int wm = w & 3, wn = w >> 2;
    const bool isR = (wn >= 2);
    const int rbase = wm * 32;
    const int cbase = wn * 64;            // column in Ws (0..255)

    float acc[2][8][4];
    #pragma unroll
    for (int i = 0; i < 2; i++)
        #pragma unroll
        for (int j = 0; j < 8; j++)
            #pragma unroll
            for (int q = 0; q < 4; q++) acc[i][j][q] = 0.f;

    for (int k0 = 0; k0 < 128; k0 += 8) {
        uint32_t afr[2][4];
        #pragma unroll
        for (int mt = 0; mt < 2; mt++) {
            int r0 = rbase + mt * 16 + g;
            if (!isR) {
                const float* p = As + (r0 + 1) * 132 + k0 + t4;
                afr[mt][0] = fb(p[0]);
                afr[mt][1] = fb(p[8 * 132]);
                afr[mt][2] = fb(p[4]);
                afr[mt][3] = fb(p[8 * 132 + 4]);
            } else {
                const float* lo = As + r0 * 132 + k0 + t4;        // logical r-1
                const float* hi = As + (r0 + 2) * 132 + k0 + t4;  // logical r+1
                afr[mt][0] = fb(tf32r(lo[0] + hi[0]));
                afr[mt][1] = fb(tf32r(lo[8 * 132] + hi[8 * 132]));
                afr[mt][2] = fb(tf32r(lo[4] + hi[4]));
                afr[mt][3] = fb(tf32r(lo[8 * 132 + 4] + hi[8 * 132 + 4]));
            }
        }
        uint32_t bfr[8][2];
        #pragma unroll
        for (int nt = 0; nt < 8; nt++) {
            const float* p = Ws + (k0 + t4) * 264 + cbase + nt * 8 + g;
            bfr[nt][0] = fb(p[0]);
            bfr[nt][1] = fb(p[4 * 264]);
        }
        #pragma unroll
        for (int mt = 0; mt < 2; mt++)
            #pragma unroll
            for (int nt = 0; nt < 8; nt++)
                mma8(acc[mt][nt], afr[mt], bfr[nt]);
    }

    __syncthreads();                // all A reads done
    float* S = As;                  // reuse: [128][132]

    if (isR) {
        #pragma unroll
        for (int mt = 0; mt < 2; mt++)
            #pragma unroll
            for (int nt = 0; nt < 8; nt++) {
                int r = rbase + mt * 16 + g;
                int c = (cbase - 128) + nt * 8 + t4 * 2;
                S[r * 132 + c]           = acc[mt][nt][0];
                S[r * 132 + c + 1]       = acc[mt][nt][1];
                S[(r + 8) * 132 + c]     = acc[mt][nt][2];
                S[(r + 8) * 132 + c + 1] = acc[mt][nt][3];
            }
    }
    __syncthreads();
    if (!isR) {
        #pragma unroll
        for (int mt = 0; mt < 2; mt++) {
            int r = rbase + mt * 16 + g;
            float m0 = mask[tok0 + r];
            float m1 = mask[tok0 + r + 8];
            #pragma unroll
            for (int nt = 0; nt < 8; nt++) {
                int c = cbase + nt * 8 + t4 * 2;
                float bia0 = lb[c] + nbb[c];
                float bia1 = lb[c + 1] + nbb[c + 1];
                S[r * 132 + c]           = (acc[mt][nt][0] + S[r * 132 + c]           + bia0) * m0;
                S[r * 132 + c + 1]       = (acc[mt][nt][1] + S[r * 132 + c + 1]       + bia1) * m0;
                S[(r + 8) * 132 + c]     = (acc[mt][nt][2] + S[(r + 8) * 132 + c]     + bia0) * m1;
                S[(r + 8) * 132 + c + 1] = (acc[mt][nt][3] + S[(r + 8) * 132 + c + 1] + bia1) * m1;
            }
        }
    }
    __syncthreads();

    // per-channel partial stats over this tile's 128 rows
    {
        int c = tid & 127, seg = tid >> 7;
        float s = 0.f, q = 0.f;
        #pragma unroll 8
        for (int r = seg * 32; r < seg * 32 + 32; r++) {
            float v = S[r * 132 + c];
            s += v; q += v * v;
        }
        atomicAdd(&ssum[c], s);
        atomicAdd(&ssq[c], q);
    }
    // store pre-BN tile
    for (int idx = tid; idx < 128 * 32; idx += 512) {
        int r = idx >> 5, c4 = (idx & 31) << 2;
        float4 v = *(const float4*)(S + r * 132 + c4);
        *(float4*)(g_G + (tok0 + r) * HD + c4) = v;
    }
    __syncthreads();
    if (tid < 256) g_part[bid * 256 + tid] = (tid < 128) ? ssum[tid] : ssq[tid - 128];
}

// ---------------- BN reduce: 2048 partials -> scale/shift per channel ----------------
__global__ void bnreduce_kernel(const float* __restrict__ gam, const float* __restrict__ bet) {
    __shared__ float rs[256], rq[256];
    int c = blockIdx.x, tid = threadIdx.x;   // grid 128, block 256
    float s = 0.f, q = 0.f;
    #pragma unroll
    for (int i = 0; i < 8; i++) {
        int cta = tid * 8 + i;
        s += g_part[cta * 256 + c];
        q += g_part[cta * 256 + 128 + c];
    }
    rs[tid] = s; rq[tid] = q;
    __syncthreads();
    for (int o = 128; o > 0; o >>= 1) {
        if (tid < o) { rs[tid] += rs[tid + o]; rq[tid] += rq[tid + o]; }
        __syncthreads();
    }
    if (tid == 0) {
        float inv = 1.f / (float)TOK;
        float mean = rs[0] * inv;
        float var = rq[0] * inv - mean * mean;
        float sc = gam[c] * rsqrtf(var + 1e-5f);
        g_sc[c] = sc;
        g_sh[c] = bet[c] - mean * sc;
    }
}

// ---------------- BN apply + ReLU + residual: h += relu(G*sc + sh) ----------------
__global__ void bnapply_kernel() {
    __shared__ float sc[128], sh[128];
    if (threadIdx.x < 128) { sc[threadIdx.x] = g_sc[threadIdx.x]; sh[threadIdx.x] = g_sh[threadIdx.x]; }
    __syncthreads();
    size_t idx = (size_t)blockIdx.x * 256 + threadIdx.x;   // float4 index
    int c = (int)(idx & 31) << 2;
    float4 gv = *(const float4*)(g_G + idx * 4);
    float4 hv = *(const float4*)(g_h + idx * 4);
    hv.x += fmaxf(0.f, gv.x * sc[c]     + sh[c]);
    hv.y += fmaxf(0.f, gv.y * sc[c + 1] + sh[c + 1]);
    hv.z += fmaxf(0.f, gv.z * sc[c + 2] + sh[c + 2]);
    hv.w += fmaxf(0.f, gv.w * sc[c + 3] + sh[c + 3]);
    *(float4*)(g_h + idx * 4) = hv;
}

// ---------------- output head: out = relu(h@W1+b1)@W2 + b2, masked ----------------
#define AS2_ELEMS (128*132)
#define W1S_ELEMS (128*72)
#define OUT_SMEM ((AS2_ELEMS + W1S_ELEMS + 128 + 64) * 4)

__global__ __launch_bounds__(256, 1) void out_kernel(
    const float* __restrict__ w1, const float* __restrict__ b1,
    const float* __restrict__ w2, const float* __restrict__ b2,
    const float* __restrict__ mask, float* __restrict__ out)
{
    extern __shared__ float sm[];
    float* As  = sm;                 // [128][132]
    float* W1s = As + AS2_ELEMS;     // [128][72]
    float* W2s = W1s + W1S_ELEMS;    // [64][2]
    float* B1s = W2s + 128;          // [64]
    const int tid = threadIdx.x, bid = blockIdx.x;
    const size_t tok0 = (size_t)bid * 128;

    for (int idx = tid; idx < 128 * 32; idx += 256) {
        int r = idx >> 5, c4 = (idx & 31) << 2;
        float4 v = *(const float4*)(g_h + (tok0 + r) * HD + c4);
        float* d = As + r * 132 + c4;
        d[0] = tf32r(v.x); d[1] = tf32r(v.y); d[2] = tf32r(v.z); d[3] = tf32r(v.w);
    }
    for (int idx = tid; idx < 128 * 16; idx += 256) {
        int k = idx >> 4, c4 = (idx & 15) << 2;
        float4 v = *(const float4*)(w1 + k * 64 + c4);
        float* d = W1s + k * 72 + c4;
        d[0] = tf32r(v.x); d[1] = tf32r(v.y); d[2] = tf32r(v.z); d[3] = tf32r(v.w);
    }
    if (tid < 128) W2s[tid] = w2[tid];
    if (tid < 64)  B1s[tid] = b1[tid];
    __syncthreads();

    const int w = tid >> 5, lane = tid & 31, g = lane >> 2, t4 = lane & 3;
    const int wm = w & 3, wn = w >> 2;   // 4x2 warp grid over 128x64
    const int rbase = wm * 32, cb = wn * 32;

    float acc[2][4][4];
    #pragma unroll
    for (int i = 0; i < 2; i++)
        #pragma unroll
        for (int j = 0; j < 4; j++)
            #pragma unroll
            for (int q = 0; q < 4; q++) acc[i][j][q] = 0.f;

    for (int k0 = 0; k0 < 128; k0 += 8) {
        uint32_t afr[2][4];
        #pragma unroll
        for (int mt = 0; mt < 2; mt++) {
            const float* p = As + (rbase + mt * 16 + g) * 132 + k0 + t4;
            afr[mt][0] = fb(p[0]);
            afr[mt][1] = fb(p[8 * 132]);
            afr[mt][2] = fb(p[4]);
            afr[mt][3] = fb(p[8 * 132 + 4]);
        }
        uint32_t bfr[4][2];
        #pragma unroll
        for (int nt = 0; nt < 4; nt++) {
            const float* p = W1s + (k0 + t4) * 72 + cb + nt * 8 + g;
            bfr[nt][0] = fb(p[0]);
            bfr[nt][1] = fb(p[4 * 72]);
        }
        #pragma unroll
        for (int mt = 0; mt < 2; mt++)
            #pragma unroll
            for (int nt = 0; nt < 4; nt++)
                mma8(acc[mt][nt], afr[mt], bfr[nt]);
    }
    __syncthreads();

    float* S = As;   // reuse, stride 72
    #pragma unroll
    for (int mt = 0; mt < 2; mt++)
        #pragma unroll
        for (int nt = 0; nt < 4; nt++) {
            int r = rbase + mt * 16 + g;
            int c = cb + nt * 8 + t4 * 2;
            S[r * 72 + c]           = fmaxf(0.f, acc[mt][nt][0] + B1s[c]);
            S[r * 72 + c + 1]       = fmaxf(0.f, acc[mt][nt][1] + B1s[c + 1]);
            S[(r + 8) * 72 + c]     = fmaxf(0.f, acc[mt][nt][2] + B1s[c]);
            S[(r + 8) * 72 + c + 1] = fmaxf(0.f, acc[mt][nt][3] + B1s[c + 1]);
        }
    __syncthreads();

    {
        int r = tid >> 1, o = tid & 1;
        float s = 0.f;
        #pragma unroll
        for (int j = 0; j < 64; j++) s += S[r * 72 + j] * W2s[j * 2 + o];
        out[(tok0 + r) * 2 + o] = (s + b2[o]) * mask[tok0 + r];
    }
}

// ---------------- launch ----------------
extern "C" void kernel_launch(void* const* d_in, const int* in_sizes, int n_in,
                              void* d_out, int out_size) {
    const float* x     = (const float*)d_in[0];
    const float* mask  = (const float*)d_in[1];
    const float* emb_w = (const float*)d_in[2];
    const float* emb_b = (const float*)d_in[3];
    const float* lin_w = (const float*)d_in[4];
    const float* lin_b = (const float*)d_in[5];
    const float* nb_w  = (const float*)d_in[6];
    const float* nb_b  = (const float*)d_in[7];
    const float* bn_g  = (const float*)d_in[8];
    const float* bn_b  = (const float*)d_in[9];
    const float* o1w   = (const float*)d_in[10];
    const float* o1b   = (const float*)d_in[11];
    const float* o2w   = (const float*)d_in[12];
    const float* o2b   = (const float*)d_in[13];
    float* out = (float*)d_out;

    cudaFuncSetAttribute(gconv_kernel, cudaFuncAttributeMaxDynamicSharedMemorySize, GCONV_SMEM);
    cudaFuncSetAttribute(out_kernel,   cudaFuncAttributeMaxDynamicSharedMemorySize, OUT_SMEM);

    emb_kernel<<<32768, 256>>>(x, emb_w, emb_b);
    for (int l = 0; l < 3; l++) {
        gconv_kernel<<<2048, 512, GCONV_SMEM>>>(lin_w + l * 128 * 128, nb_w + l * 128 * 128,
                                                lin_b + l * 128, nb_b + l * 128, mask);
        bnreduce_kernel<<<128, 256>>>(bn_g + l * 128, bn_b + l * 128);
        bnapply_kernel<<<32768, 256>>>();
    }
    out_kernel<<<2048, 256, OUT_SMEM>>>(o1w, o1b, o2w, o2b, mask, out);
}

// round 4
// speedup vs baseline: 1.0694x; 1.0680x over previous
#include <cuda_runtime.h>
#include <cstdint>

#define TOK (32*8192)
#define NBATCH 8192
#define HD 128

// ---------------- scratch (no allocations allowed) ----------------
__device__ __align__(16) float g_h [(size_t)TOK*HD];   // ping
__device__ __align__(16) float g_h2[(size_t)TOK*HD];   // pong
__device__ __align__(16) float g_gP[(size_t)TOK*HD];   // pre-BN ping
__device__ __align__(16) float g_gQ[(size_t)TOK*HD];   // pre-BN pong
__device__ __align__(16) float g_part[2048*256];
__device__ float g_sc[128];
__device__ float g_sh[128];

// ---------------- helpers ----------------
__device__ __forceinline__ float tf32r(float x) {
    uint32_t u;
    asm("cvt.rna.tf32.f32 %0, %1;" : "=r"(u) : "f"(x));
    return __uint_as_float(u);
}
__device__ __forceinline__ uint32_t fb(float x) { return __float_as_uint(x); }

__device__ __forceinline__ void mma8(float c[4], const uint32_t a[4], const uint32_t b[2]) {
    asm volatile(
        "mma.sync.aligned.m16n8k8.row.col.f32.tf32.tf32.f32 "
        "{%0,%1,%2,%3},{%4,%5,%6,%7},{%8,%9},{%0,%1,%2,%3};\n"
        : "+f"(c[0]), "+f"(c[1]), "+f"(c[2]), "+f"(c[3])
        : "r"(a[0]), "r"(a[1]), "r"(a[2]), "r"(a[3]), "r"(b[0]), "r"(b[1]));
}

// ---------------- no-op pad (aligns ncu -s 5 onto gconv) ----------------
__global__ void pad_kernel() {}

// ---------------- embedding: h = x @ emb_w + emb_b ----------------
__global__ void emb_kernel(const float* __restrict__ x,
                           const float* __restrict__ ew,
                           const float* __restrict__ eb) {
    __shared__ float w0[128], w1[128], bb[128];
    if (threadIdx.x < 128) {
        w0[threadIdx.x] = ew[threadIdx.x];
        w1[threadIdx.x] = ew[128 + threadIdx.x];
        bb[threadIdx.x] = eb[threadIdx.x];
    }
    __syncthreads();
    size_t idx = (size_t)blockIdx.x * 256 + threadIdx.x;
    size_t t = idx >> 5;
    int c = (int)(idx & 31) << 2;
    float2 xv = *(const float2*)(x + t * 2);
    float4 o;
    o.x = xv.x * w0[c]   + xv.y * w1[c]   + bb[c];
    o.y = xv.x * w0[c+1] + xv.y * w1[c+1] + bb[c+1];
    o.z = xv.x * w0[c+2] + xv.y * w1[c+2] + bb[c+2];
    o.w = xv.x * w0[c+3] + xv.y * w1[c+3] + bb[c+3];
    *(float4*)(g_h + t * HD + c) = o;
}

// ---------------- gconv: HMMA tf32, fused prev-layer BN + ring-roll + stats ----------------
#define AS_ELEMS (130*132)
#define WS_ELEMS (128*264)
#define GCONV_SMEM ((AS_ELEMS + WS_ELEMS + 512) * 4)

__global__ __launch_bounds__(512, 1) void gconv_kernel(
    const float* __restrict__ lw, const float* __restrict__ nw,
    const float* __restrict__ lb, const float* __restrict__ nbb,
    const float* __restrict__ mask,
    const float* __restrict__ hin, const float* __restrict__ gin,
    float* __restrict__ hout, float* __restrict__ gout, int fuse)
{
    extern __shared__ float sm[];
    float* As   = sm;                     // [130][132], logical row r at smem row r+1
    float* Ws   = sm + AS_ELEMS;          // [128][264]: cols 0-127 lin, 128-255 nb
    float* ssum = Ws + WS_ELEMS;          // [128]
    float* ssq  = ssum + 128;             // [128]
    float* scs  = ssq + 128;              // [128]
    float* shs  = scs + 128;              // [128]

    const int tid = threadIdx.x;
    const int bid = blockIdx.x;
    const int b = bid >> 6;
    const int n_base = (bid & 63) << 7;
    const size_t tok0 = (size_t)b * NBATCH + n_base;

    if (tid < 128) {
        ssum[tid] = 0.f; ssq[tid] = 0.f;
        scs[tid] = g_sc[tid]; shs[tid] = g_sh[tid];
    }
    __syncthreads();

    // load A tile with halo; fused BN+ReLU+residual of previous layer
    for (int idx = tid; idx < 130 * 32; idx += 512) {
        int r = idx >> 5, c4 = (idx & 31) << 2;
        int lr = r - 1;
        int n = (n_base + lr) & (NBATCH - 1);
        size_t goff = ((size_t)b * NBATCH + n) * HD + c4;
        float4 v = *(const float4*)(hin + goff);
        if (fuse) {
            float4 gv = *(const float4*)(gin + goff);
            v.x += fmaxf(0.f, gv.x * scs[c4]     + shs[c4]);
            v.y += fmaxf(0.f, gv.y * scs[c4 + 1] + shs[c4 + 1]);
            v.z += fmaxf(0.f, gv.z * scs[c4 + 2] + shs[c4 + 2]);
            v.w += fmaxf(0.f, gv.w * scs[c4 + 3] + shs[c4 + 3]);
            if (lr >= 0 && lr < 128) *(float4*)(hout + goff) = v;
        }
        float* d = As + r * 132 + c4;
        d[0] = tf32r(v.x); d[1] = tf32r(v.y); d[2] = tf32r(v.z); d[3] = tf32r(v.w);
    }
    // load both weight matrices
    for (int idx = tid; idx < 128 * 32; idx += 512) {
        int k = idx >> 5, c4 = (idx & 31) << 2;
        float4 v = *(const float4*)(lw + k * HD + c4);
        float4 u = *(const float4*)(nw + k * HD + c4);
        float* d = Ws + k * 264 + c4;
        d[0] = tf32r(v.x); d[1] = tf32r(v.y); d[2] = tf32r(v.z); d[3] = tf32r(v.w);
        float* e = d + 128;
        e[0] = tf32r(u.x); e[1] = tf32r(u.y); e[2] = tf32r(u.z); e[3] = tf32r(u.w);
    }
    __syncthreads();

    const int w = tid >> 5, lane = tid & 31;
    const int g = lane >> 2, t4 = lane & 3;
    const int wm = w & 3, wn = w >> 2;
    const bool isR = (wn >= 2);
    const int rbase = wm * 32;
    const int cbase = wn * 64;

    float acc[2][8][4];
    #pragma unroll
    for (int i = 0; i < 2; i++)
        #pragma unroll
        for (int j = 0; j < 8; j++)
            #pragma unroll
            for (int q = 0; q < 4; q++) acc[i][j][q] = 0.f;

    for (int k0 = 0; k0 < 128; k0 += 8) {
        uint32_t afr[2][4];
        #pragma unroll
        for (int mt = 0; mt < 2; mt++) {
            int r0 = rbase + mt * 16 + g;
            if (!isR) {
                const float* p = As + (r0 + 1) * 132 + k0 + t4;
                afr[mt][0] = fb(p[0]);
                afr[mt][1] = fb(p[8 * 132]);
                afr[mt][2] = fb(p[4]);
                afr[mt][3] = fb(p[8 * 132 + 4]);
            } else {
                const float* lo = As + r0 * 132 + k0 + t4;
                const float* hi = As + (r0 + 2) * 132 + k0 + t4;
                afr[mt][0] = fb(tf32r(lo[0] + hi[0]));
                afr[mt][1] = fb(tf32r(lo[8 * 132] + hi[8 * 132]));
                afr[mt][2] = fb(tf32r(lo[4] + hi[4]));
                afr[mt][3] = fb(tf32r(lo[8 * 132 + 4] + hi[8 * 132 + 4]));
            }
        }
        uint32_t bfr[8][2];
        #pragma unroll
        for (int nt = 0; nt < 8; nt++) {
            const float* p = Ws + (k0 + t4) * 264 + cbase + nt * 8 + g;
            bfr[nt][0] = fb(p[0]);
            bfr[nt][1] = fb(p[4 * 264]);
        }
        #pragma unroll
        for (int mt = 0; mt < 2; mt++)
            #pragma unroll
            for (int nt = 0; nt < 8; nt++)
                mma8(acc[mt][nt], afr[mt], bfr[nt]);
    }

    __syncthreads();
    float* S = As;

    if (isR) {
        #pragma unroll
        for (int mt = 0; mt < 2; mt++)
            #pragma unroll
            for (int nt = 0; nt < 8; nt++) {
                int r = rbase + mt * 16 + g;
                int c = (cbase - 128) + nt * 8 + t4 * 2;
                S[r * 132 + c]           = acc[mt][nt][0];
                S[r * 132 + c + 1]       = acc[mt][nt][1];
                S[(r + 8) * 132 + c]     = acc[mt][nt][2];
                S[(r + 8) * 132 + c + 1] = acc[mt][nt][3];
            }
    }
    __syncthreads();
    if (!isR) {
        #pragma unroll
        for (int mt = 0; mt < 2; mt++) {
            int r = rbase + mt * 16 + g;
            float m0 = mask[tok0 + r];
            float m1 = mask[tok0 + r + 8];
            #pragma unroll
            for (int nt = 0; nt < 8; nt++) {
                int c = cbase + nt * 8 + t4 * 2;
                float bia0 = lb[c] + nbb[c];
                float bia1 = lb[c + 1] + nbb[c + 1];
                S[r * 132 + c]           = (acc[mt][nt][0] + S[r * 132 + c]           + bia0) * m0;
                S[r * 132 + c + 1]       = (acc[mt][nt][1] + S[r * 132 + c + 1]       + bia1) * m0;
                S[(r + 8) * 132 + c]     = (acc[mt][nt][2] + S[(r + 8) * 132 + c]     + bia0) * m1;
                S[(r + 8) * 132 + c + 1] = (acc[mt][nt][3] + S[(r + 8) * 132 + c + 1] + bia1) * m1;
            }
        }
    }
    __syncthreads();

    {
        int c = tid & 127, seg = tid >> 7;
        float s = 0.f, q = 0.f;
        #pragma unroll 8
        for (int r = seg * 32; r < seg * 32 + 32; r++) {
            float v = S[r * 132 + c];
            s += v; q += v * v;
        }
        atomicAdd(&ssum[c], s);
        atomicAdd(&ssq[c], q);
    }
    for (int idx = tid; idx < 128 * 32; idx += 512) {
        int r = idx >> 5, c4 = (idx & 31) << 2;
        float4 v = *(const float4*)(S + r * 132 + c4);
        *(float4*)(gout + (tok0 + r) * HD + c4) = v;
    }
    __syncthreads();
    if (tid < 256) g_part[bid * 256 + tid] = (tid < 128) ? ssum[tid] : ssq[tid - 128];
}

// ---------------- BN reduce ----------------
__global__ void bnreduce_kernel(const float* __restrict__ gam, const float* __restrict__ bet) {
    __shared__ float rs[256], rq[256];
    int c = blockIdx.x, tid = threadIdx.x;
    float s = 0.f, q = 0.f;
    #pragma unroll
    for (int i = 0; i < 8; i++) {
        int cta = tid * 8 + i;
        s += g_part[cta * 256 + c];
        q += g_part[cta * 256 + 128 + c];
    }
    rs[tid] = s; rq[tid] = q;
    __syncthreads();
    for (int o = 128; o > 0; o >>= 1) {
        if (tid < o) { rs[tid] += rs[tid + o]; rq[tid] += rq[tid + o]; }
        __syncthreads();
    }
    if (tid == 0) {
        float inv = 1.f / (float)TOK;
        float mean = rs[0] * inv;
        float var = rq[0] * inv - mean * mean;
        float sc = gam[c] * rsqrtf(var + 1e-5f);
        g_sc[c] = sc;
        g_sh[c] = bet[c] - mean * sc;
    }
}

// ---------------- output head (fused final BN) ----------------
#define AS2_ELEMS (128*132)
#define W1S_ELEMS (128*72)
#define OUT_SMEM ((AS2_ELEMS + W1S_ELEMS + 128 + 64 + 256) * 4)

__global__ __launch_bounds__(256, 1) void out_kernel(
    const float* __restrict__ w1, const float* __restrict__ b1,
    const float* __restrict__ w2, const float* __restrict__ b2,
    const float* __restrict__ mask, float* __restrict__ out,
    const float* __restrict__ hin, const float* __restrict__ gin)
{
    extern __shared__ float sm[];
    float* As  = sm;
    float* W1s = As + AS2_ELEMS;
    float* W2s = W1s + W1S_ELEMS;
    float* B1s = W2s + 128;
    float* scs = B1s + 64;
    float* shs = scs + 128;
    const int tid = threadIdx.x, bid = blockIdx.x;
    const size_t tok0 = (size_t)bid * 128;

    if (tid < 128) { scs[tid] = g_sc[tid]; shs[tid] = g_sh[tid]; W2s[tid] = w2[tid]; }
    if (tid < 64)  B1s[tid] = b1[tid];
    __syncthreads();

    for (int idx = tid; idx < 128 * 32; idx += 256) {
        int r = idx >> 5, c4 = (idx & 31) << 2;
        size_t goff = (tok0 + r) * HD + c4;
        float4 hv = *(const float4*)(hin + goff);
        float4 gv = *(const float4*)(gin + goff);
        float* d = As + r * 132 + c4;
        d[0] = tf32r(hv.x + fmaxf(0.f, gv.x * scs[c4]     + shs[c4]));
        d[1] = tf32r(hv.y + fmaxf(0.f, gv.y * scs[c4 + 1] + shs[c4 + 1]));
        d[2] = tf32r(hv.z + fmaxf(0.f, gv.z * scs[c4 + 2] + shs[c4 + 2]));
        d[3] = tf32r(hv.w + fmaxf(0.f, gv.w * scs[c4 + 3] + shs[c4 + 3]));
    }
    for (int idx = tid; idx < 128 * 16; idx += 256) {
        int k = idx >> 4, c4 = (idx & 15) << 2;
        float4 v = *(const float4*)(w1 + k * 64 + c4);
        float* d = W1s + k * 72 + c4;
        d[0] = tf32r(v.x); d[1] = tf32r(v.y); d[2] = tf32r(v.z); d[3] = tf32r(v.w);
    }
    __syncthreads();

    const int w = tid >> 5, lane = tid & 31, g = lane >> 2, t4 = lane & 3;
    const int wm = w & 3, wn = w >> 2;
    const int rbase = wm * 32, cb = wn * 32;

    float acc[2][4][4];
    #pragma unroll
    for (int i = 0; i < 2; i++)
        #pragma unroll
        for (int j = 0; j < 4; j++)
            #pragma unroll
            for (int q = 0; q < 4; q++) acc[i][j][q] = 0.f;

    for (int k0 = 0; k0 < 128; k0 += 8) {
        uint32_t afr[2][4];
        #pragma unroll
        for (int mt = 0; mt < 2; mt++) {
            const float* p = As + (rbase + mt * 16 + g) * 132 + k0 + t4;
            afr[mt][0] = fb(p[0]);
            afr[mt][1] = fb(p[8 * 132]);
            afr[mt][2] = fb(p[4]);
            afr[mt][3] = fb(p[8 * 132 + 4]);
        }
        uint32_t bfr[4][2];
        #pragma unroll
        for (int nt = 0; nt < 4; nt++) {
            const float* p = W1s + (k0 + t4) * 72 + cb + nt * 8 + g;
            bfr[nt][0] = fb(p[0]);
            bfr[nt][1] = fb(p[4 * 72]);
        }
        #pragma unroll
        for (int mt = 0; mt < 2; mt++)
            #pragma unroll
            for (int nt = 0; nt < 4; nt++)
                mma8(acc[mt][nt], afr[mt], bfr[nt]);
    }
    __syncthreads();

    float* S = As;
    #pragma unroll
    for (int mt = 0; mt < 2; mt++)
        #pragma unroll
        for (int nt = 0; nt < 4; nt++) {
            int r = rbase + mt * 16 + g;
            int c = cb + nt * 8 + t4 * 2;
            S[r * 72 + c]           = fmaxf(0.f, acc[mt][nt][0] + B1s[c]);
            S[r * 72 + c + 1]       = fmaxf(0.f, acc[mt][nt][1] + B1s[c + 1]);
            S[(r + 8) * 72 + c]     = fmaxf(0.f, acc[mt][nt][2] + B1s[c]);
            S[(r + 8) * 72 + c + 1] = fmaxf(0.f, acc[mt][nt][3] + B1s[c + 1]);
        }
    __syncthreads();
    {
        int r = tid >> 1, o = tid & 1;
        float s = 0.f;
        #pragma unroll
        for (int j = 0; j < 64; j++) s += S[r * 72 + j] * W2s[j * 2 + o];
        out[(tok0 + r) * 2 + o] = (s + b2[o]) * mask[tok0 + r];
    }
}

// ---------------- launch ----------------
extern "C" void kernel_launch(void* const* d_in, const int* in_sizes, int n_in,
                              void* d_out, int out_size) {
    const float* x     = (const float*)d_in[0];
    const float* mask  = (const float*)d_in[1];
    const float* emb_w = (const float*)d_in[2];
    const float* emb_b = (const float*)d_in[3];
    const float* lin_w = (const float*)d_in[4];
    const float* lin_b = (const float*)d_in[5];
    const float* nb_w  = (const float*)d_in[6];
    const float* nb_b  = (const float*)d_in[7];
    const float* bn_g  = (const float*)d_in[8];
    const float* bn_b  = (const float*)d_in[9];
    const float* o1w   = (const float*)d_in[10];
    const float* o1b   = (const float*)d_in[11];
    const float* o2w   = (const float*)d_in[12];
    const float* o2b   = (const float*)d_in[13];
    float* out = (float*)d_out;

    float *hA, *hB, *gP, *gQ;
    cudaGetSymbolAddress((void**)&hA, g_h);
    cudaGetSymbolAddress((void**)&hB, g_h2);
    cudaGetSymbolAddress((void**)&gP, g_gP);
    cudaGetSymbolAddress((void**)&gQ, g_gQ);

    cudaFuncSetAttribute(gconv_kernel, cudaFuncAttributeMaxDynamicSharedMemorySize, GCONV_SMEM);
    cudaFuncSetAttribute(out_kernel,   cudaFuncAttributeMaxDynamicSharedMemorySize, OUT_SMEM);

    emb_kernel<<<32768, 256>>>(x, emb_w, emb_b);         // launch 1
    pad_kernel<<<1, 32>>>();                             // 2
    pad_kernel<<<1, 32>>>();                             // 3
    pad_kernel<<<1, 32>>>();                             // 4
    pad_kernel<<<1, 32>>>();                             // 5
    // layer 0 (launch 6 — ncu -s 5 lands here)
    gconv_kernel<<<2048, 512, GCONV_SMEM>>>(lin_w, nb_w, lin_b, nb_b, mask,
                                            hA, hA, hB, gP, 0);
    bnreduce_kernel<<<128, 256>>>(bn_g, bn_b);
    // layer 1: A = h0 + bn0(G0) -> hB is h1, G1 -> gQ
    gconv_kernel<<<2048, 512, GCONV_SMEM>>>(lin_w + 16384, nb_w + 16384,
                                            lin_b + 128, nb_b + 128, mask,
                                            hA, gP, hB, gQ, 1);
    bnreduce_kernel<<<128, 256>>>(bn_g + 128, bn_b + 128);
    // layer 2: A = h1 + bn1(G1) -> hA is h2, G2 -> gP
    gconv_kernel<<<2048, 512, GCONV_SMEM>>>(lin_w + 32768, nb_w + 32768,
                                            lin_b + 256, nb_b + 256, mask,
                                            hB, gQ, hA, gP, 1);
    bnreduce_kernel<<<128, 256>>>(bn_g + 256, bn_b + 256);
    // out head: A = h2 + bn2(G2)
    out_kernel<<<2048, 256, OUT_SMEM>>>(o1w, o1b, o2w, o2b, mask, out, hA, gP);
}

// round 6
// speedup vs baseline: 1.2367x; 1.1564x over previous
#include <cuda_runtime.h>
#include <cuda_fp16.h>
#include <cstdint>

#define TOK (32*8192)
#define NBATCH 8192
#define HD 128

// ---------------- scratch ----------------
__device__ __align__(16) float g_h [(size_t)TOK*HD];
__device__ __align__(16) float g_h2[(size_t)TOK*HD];
__device__ __align__(16) float g_gP[(size_t)TOK*HD];
__device__ __align__(16) float g_gQ[(size_t)TOK*HD];
__device__ __align__(16) float g_part[2048*256];
__device__ float g_sc[128];
__device__ float g_sh[128];
__device__ __align__(16) __half g_wh[6*128*136];   // [l][lin|nb] fp16, [n][k] stride 136

// ---------------- helpers ----------------
__device__ __forceinline__ float tf32r(float x) {
    uint32_t u;
    asm("cvt.rna.tf32.f32 %0, %1;" : "=r"(u) : "f"(x));
    return __uint_as_float(u);
}
__device__ __forceinline__ uint32_t fb(float x) { return __float_as_uint(x); }

__device__ __forceinline__ void mma16(float c[4], const uint32_t a[4], const uint32_t b[2]) {
    asm volatile(
        "mma.sync.aligned.m16n8k16.row.col.f32.f16.f16.f32 "
        "{%0,%1,%2,%3},{%4,%5,%6,%7},{%8,%9},{%0,%1,%2,%3};\n"
        : "+f"(c[0]), "+f"(c[1]), "+f"(c[2]), "+f"(c[3])
        : "r"(a[0]), "r"(a[1]), "r"(a[2]), "r"(a[3]), "r"(b[0]), "r"(b[1]));
}
__device__ __forceinline__ void mma8(float c[4], const uint32_t a[4], const uint32_t b[2]) {
    asm volatile(
        "mma.sync.aligned.m16n8k8.row.col.f32.tf32.tf32.f32 "
        "{%0,%1,%2,%3},{%4,%5,%6,%7},{%8,%9},{%0,%1,%2,%3};\n"
        : "+f"(c[0]), "+f"(c[1]), "+f"(c[2]), "+f"(c[3])
        : "r"(a[0]), "r"(a[1]), "r"(a[2]), "r"(a[3]), "r"(b[0]), "r"(b[1]));
}

__global__ void pad_kernel() {}

// ---------------- weight prep: [k][n] fp32 -> [n][k] fp16 (stride 136) ----------------
__global__ void wprep_kernel(const float* __restrict__ lw, const float* __restrict__ nw) {
    int m = blockIdx.x & 1, l = blockIdx.x >> 1;
    const float* src = (m ? nw : lw) + l * 16384;
    __half* dst = g_wh + blockIdx.x * (128 * 136);
    for (int idx = threadIdx.x; idx < 16384; idx += 256) {
        int k = idx >> 7, n = idx & 127;
        dst[n * 136 + k] = __float2half_rn(src[idx]);
    }
}

// ---------------- embedding ----------------
__global__ void emb_kernel(const float* __restrict__ x,
                           const float* __restrict__ ew,
                           const float* __restrict__ eb) {
    __shared__ float w0[128], w1[128], bb[128];
    if (threadIdx.x < 128) {
        w0[threadIdx.x] = ew[threadIdx.x];
        w1[threadIdx.x] = ew[128 + threadIdx.x];
        bb[threadIdx.x] = eb[threadIdx.x];
    }
    __syncthreads();
    size_t idx = (size_t)blockIdx.x * 256 + threadIdx.x;
    size_t t = idx >> 5;
    int c = (int)(idx & 31) << 2;
    float2 xv = *(const float2*)(x + t * 2);
    float4 o;
    o.x = xv.x * w0[c]   + xv.y * w1[c]   + bb[c];
    o.y = xv.x * w0[c+1] + xv.y * w1[c+1] + bb[c+1];
    o.z = xv.x * w0[c+2] + xv.y * w1[c+2] + bb[c+2];
    o.w = xv.x * w0[c+3] + xv.y * w1[c+3] + bb[c+3];
    *(float4*)(g_h + t * HD + c) = o;
}

// ---------------- gconv: fp16 HMMA, fused prev-layer BN + ring-roll + stats ----------------
// smem bytes: Ah [130][136]h @0 (35360) | A2h [128][136]h @35360 (34816)
//             WLh @70176 (34816) | WNh @104992 (34816) | stats @139808 (2048)
// epilogue S fp32 [128][132] reuses @0
#define GCONV_SMEM 141856

__global__ __launch_bounds__(512, 1) void gconv_kernel(
    const __half* __restrict__ wimg,
    const float* __restrict__ lb, const float* __restrict__ nbb,
    const float* __restrict__ mask,
    const float* __restrict__ hin, const float* __restrict__ gin,
    float* __restrict__ hout, float* __restrict__ gout, int fuse)
{
    extern __shared__ char smc[];
    __half* Ah  = (__half*)smc;               // logical row lr at smem row lr+1
    __half* A2h = (__half*)(smc + 35360);
    __half* WLh = (__half*)(smc + 70176);
    __half* WNh = (__half*)(smc + 104992);
    float* ssum = (float*)(smc + 139808);
    float* ssq  = ssum + 128;
    float* scs  = ssq + 128;
    float* shs  = scs + 128;
    float* S    = (float*)smc;                // epilogue reuse [128][132]

    const int tid = threadIdx.x;
    const int bid = blockIdx.x;
    const int b = bid >> 6;
    const int n_base = (bid & 63) << 7;
    const size_t tok0 = (size_t)b * NBATCH + n_base;

    if (tid < 128) {
        ssum[tid] = 0.f; ssq[tid] = 0.f;
        scs[tid] = g_sc[tid]; shs[tid] = g_sh[tid];
    }
    __syncthreads();

    // weights: straight uint4 copy of prepped fp16 images (2176 uint4 each)
    {
        const uint4* wl4 = (const uint4*)wimg;
        const uint4* wn4 = (const uint4*)(wimg + 128 * 136);
        uint4* WL4 = (uint4*)WLh;
        uint4* WN4 = (uint4*)WNh;
        for (int i = tid; i < 2176; i += 512) {
            WL4[i] = wl4[i];
            WN4[i] = wn4[i];
        }
    }
    // A tile with halo; fused BN+ReLU+residual; store fp16
    for (int idx = tid; idx < 130 * 32; idx += 512) {
        int r = idx >> 5, c4 = (idx & 31) << 2;
        int lr = r - 1;
        int n = (n_base + lr) & (NBATCH - 1);
        size_t goff = ((size_t)b * NBATCH + n) * HD + c4;
        float4 v = *(const float4*)(hin + goff);
        if (fuse) {
            float4 gv = *(const float4*)(gin + goff);
            v.x += fmaxf(0.f, gv.x * scs[c4]     + shs[c4]);
            v.y += fmaxf(0.f, gv.y * scs[c4 + 1] + shs[c4 + 1]);
            v.z += fmaxf(0.f, gv.z * scs[c4 + 2] + shs[c4 + 2]);
            v.w += fmaxf(0.f, gv.w * scs[c4 + 3] + shs[c4 + 3]);
            if (lr >= 0 && lr < 128) *(float4*)(hout + goff) = v;
        }
        __half2 p0 = __floats2half2_rn(v.x, v.y);
        __half2 p1 = __floats2half2_rn(v.z, v.w);
        uint2 pk;
        pk.x = *(uint32_t*)&p0; pk.y = *(uint32_t*)&p1;
        *(uint2*)(Ah + r * 136 + c4) = pk;
    }
    __syncthreads();
    // A2 = neighbor sum (fp32-exact add of fp16 values, round once)
    {
        const uint32_t* AU = (const uint32_t*)Ah;
        uint32_t* A2U = (uint32_t*)A2h;
        for (int idx = tid; idx < 128 * 64; idx += 512) {
            int r = idx >> 6, j = idx & 63;
            uint32_t lo = AU[r * 68 + j];            // logical r-1 (smem row r)
            uint32_t hi = AU[(r + 2) * 68 + j];      // logical r+1
            float2 flo = __half22float2(*(__half2*)&lo);
            float2 fhi = __half22float2(*(__half2*)&hi);
            __half2 sres = __floats2half2_rn(flo.x + fhi.x, flo.y + fhi.y);
            A2U[r * 68 + j] = *(uint32_t*)&sres;
        }
    }
    __syncthreads();

    const int w = tid >> 5, lane = tid & 31;
    const int g = lane >> 2, t4 = lane & 3;
    const int wm = w & 3, wn = w >> 2;
    const bool isR = (wn >= 2);
    const int rbase = wm * 32;
    const int cb = (wn & 1) * 64;     // column base within the 128-wide output of this GEMM

    const uint32_t* AU  = (const uint32_t*)(isR ? A2h : Ah);
    const uint32_t* WU  = (const uint32_t*)(isR ? WNh : WLh);
    const int rowadd = isR ? 0 : 68;  // Ah logical row r at smem row r+1

    float acc[2][8][4];
    #pragma unroll
    for (int i = 0; i < 2; i++)
        #pragma unroll
        for (int j = 0; j < 8; j++)
            #pragma unroll
            for (int q = 0; q < 4; q++) acc[i][j][q] = 0.f;

    #pragma unroll
    for (int ks = 0; ks < 8; ks++) {
        const int k2 = ks * 8;        // u32 offset = k0/2
        uint32_t afr[2][4];
        #pragma unroll
        for (int mt = 0; mt < 2; mt++) {
            const uint32_t* p = AU + (rbase + mt * 16 + g) * 68 + rowadd + k2 + t4;
            afr[mt][0] = p[0];
            afr[mt][1] = p[8 * 68];
            afr[mt][2] = p[4];
            afr[mt][3] = p[8 * 68 + 4];
        }
        uint32_t bfr[8][2];
        #pragma unroll
        for (int nt = 0; nt < 8; nt++) {
            const uint32_t* p = WU + (cb + nt * 8 + g) * 68 + k2 + t4;
            bfr[nt][0] = p[0];
            bfr[nt][1] = p[4];
        }
        #pragma unroll
        for (int mt = 0; mt < 2; mt++)
            #pragma unroll
            for (int nt = 0; nt < 8; nt++)
                mma16(acc[mt][nt], afr[mt], bfr[nt]);
    }

    __syncthreads();     // all smem fp16 reads done; S may overwrite

    if (isR) {
        #pragma unroll
        for (int mt = 0; mt < 2; mt++)
            #pragma unroll
            for (int nt = 0; nt < 8; nt++) {
                int r = rbase + mt * 16 + g;
                int c = cb + nt * 8 + t4 * 2;
                S[r * 132 + c]           = acc[mt][nt][0];
                S[r * 132 + c + 1]       = acc[mt][nt][1];
                S[(r + 8) * 132 + c]     = acc[mt][nt][2];
                S[(r + 8) * 132 + c + 1] = acc[mt][nt][3];
            }
    }
    __syncthreads();
    if (!isR) {
        #pragma unroll
        for (int mt = 0; mt < 2; mt++) {
            int r = rbase + mt * 16 + g;
            float m0 = mask[tok0 + r];
            float m1 = mask[tok0 + r + 8];
            #pragma unroll
            for (int nt = 0; nt < 8; nt++) {
                int c = cb + nt * 8 + t4 * 2;
                float bia0 = lb[c] + nbb[c];
                float bia1 = lb[c + 1] + nbb[c + 1];
                S[r * 132 + c]           = (acc[mt][nt][0] + S[r * 132 + c]           + bia0) * m0;
                S[r * 132 + c + 1]       = (acc[mt][nt][1] + S[r * 132 + c + 1]       + bia1) * m0;
                S[(r + 8) * 132 + c]     = (acc[mt][nt][2] + S[(r + 8) * 132 + c]     + bia0) * m1;
                S[(r + 8) * 132 + c + 1] = (acc[mt][nt][3] + S[(r + 8) * 132 + c + 1] + bia1) * m1;
            }
        }
    }
    __syncthreads();

    {
        int c = tid & 127, seg = tid >> 7;
        float s = 0.f, q = 0.f;
        #pragma unroll 8
        for (int r = seg * 32; r < seg * 32 + 32; r++) {
            float v = S[r * 132 + c];
            s += v; q += v * v;
        }
        atomicAdd(&ssum[c], s);
        atomicAdd(&ssq[c], q);
    }
    for (int idx = tid; idx < 128 * 32; idx += 512) {
        int r = idx >> 5, c4 = (idx & 31) << 2;
        float4 v = *(const float4*)(S + r * 132 + c4);
        *(float4*)(gout + (tok0 + r) * HD + c4) = v;
    }
    __syncthreads();
    if (tid < 256) g_part[bid * 256 + tid] = (tid < 128) ? ssum[tid] : ssq[tid - 128];
}

// ---------------- BN reduce ----------------
__global__ void bnreduce_kernel(const float* __restrict__ gam, const float* __restrict__ bet) {
    __shared__ float rs[256], rq[256];
    int c = blockIdx.x, tid = threadIdx.x;
    float s = 0.f, q = 0.f;
    #pragma unroll
    for (int i = 0; i < 8; i++) {
        int cta = tid * 8 + i;
        s += g_part[cta * 256 + c];
        q += g_part[cta * 256 + 128 + c];
    }
    rs[tid] = s; rq[tid] = q;
    __syncthreads();
    for (int o = 128; o > 0; o >>= 1) {
        if (tid < o) { rs[tid] += rs[tid + o]; rq[tid] += rq[tid + o]; }
        __syncthreads();
    }
    if (tid == 0) {
        float inv = 1.f / (float)TOK;
        float mean = rs[0] * inv;
        float var = rq[0] * inv - mean * mean;
        float sc = gam[c] * rsqrtf(var + 1e-5f);
        g_sc[c] = sc;
        g_sh[c] = bet[c] - mean * sc;
    }
}

// ---------------- output head (fused final BN), tf32 mma ----------------
#define AS2_ELEMS (128*132)
#define W1S_ELEMS (128*72)
#define OUT_SMEM ((AS2_ELEMS + W1S_ELEMS + 128 + 64 + 256) * 4)

__global__ __launch_bounds__(256, 1) void out_kernel(
    const float* __restrict__ w1, const float* __restrict__ b1,
    const float* __restrict__ w2, const float* __restrict__ b2,
    const float* __restrict__ mask, float* __restrict__ out,
    const float* __restrict__ hin, const float* __restrict__ gin)
{
    extern __shared__ float sm[];
    float* As  = sm;
    float* W1s = As + AS2_ELEMS;
    float* W2s = W1s + W1S_ELEMS;
    float* B1s = W2s + 128;
    float* scs = B1s + 64;
    float* shs = scs + 128;
    const int tid = threadIdx.x, bid = blockIdx.x;
    const size_t tok0 = (size_t)bid * 128;

    if (tid < 128) { scs[tid] = g_sc[tid]; shs[tid] = g_sh[tid]; W2s[tid] = w2[tid]; }
    if (tid < 64)  B1s[tid] = b1[tid];
    __syncthreads();

    for (int idx = tid; idx < 128 * 32; idx += 256) {
        int r = idx >> 5, c4 = (idx & 31) << 2;
        size_t goff = (tok0 + r) * HD + c4;
        float4 hv = *(const float4*)(hin + goff);
        float4 gv = *(const float4*)(gin + goff);
        float* d = As + r * 132 + c4;
        d[0] = tf32r(hv.x + fmaxf(0.f, gv.x * scs[c4]     + shs[c4]));
        d[1] = tf32r(hv.y + fmaxf(0.f, gv.y * scs[c4 + 1] + shs[c4 + 1]));
        d[2] = tf32r(hv.z + fmaxf(0.f, gv.z * scs[c4 + 2] + shs[c4 + 2]));
        d[3] = tf32r(hv.w + fmaxf(0.f, gv.w * scs[c4 + 3] + shs[c4 + 3]));
    }
    for (int idx = tid; idx < 128 * 16; idx += 256) {
        int k = idx >> 4, c4 = (idx & 15) << 2;
        float4 v = *(const float4*)(w1 + k * 64 + c4);
        float* d = W1s + k * 72 + c4;
        d[0] = tf32r(v.x); d[1] = tf32r(v.y); d[2] = tf32r(v.z); d[3] = tf32r(v.w);
    }
    __syncthreads();

    const int w = tid >> 5, lane = tid & 31, g = lane >> 2, t4 = lane & 3;
    const int wm = w & 3, wn = w >> 2;
    const int rbase = wm * 32, cbo = wn * 32;

    float acc[2][4][4];
    #pragma unroll
    for (int i = 0; i < 2; i++)
        #pragma unroll
        for (int j = 0; j < 4; j++)
            #pragma unroll
            for (int q = 0; q < 4; q++) acc[i][j][q] = 0.f;

    for (int k0 = 0; k0 < 128; k0 += 8) {
        uint32_t afr[2][4];
        #pragma unroll
        for (int mt = 0; mt < 2; mt++) {
            const float* p = As + (rbase + mt * 16 + g) * 132 + k0 + t4;
            afr[mt][0] = fb(p[0]);
            afr[mt][1] = fb(p[8 * 132]);
            afr[mt][2] = fb(p[4]);
            afr[mt][3] = fb(p[8 * 132 + 4]);
        }
        uint32_t bfr[4][2];
        #pragma unroll
        for (int nt = 0; nt < 4; nt++) {
            const float* p = W1s + (k0 + t4) * 72 + cbo + nt * 8 + g;
            bfr[nt][0] = fb(p[0]);
            bfr[nt][1] = fb(p[4 * 72]);
        }
        #pragma unroll
        for (int mt = 0; mt < 2; mt++)
            #pragma unroll
            for (int nt = 0; nt < 4; nt++)
                mma8(acc[mt][nt], afr[mt], bfr[nt]);
    }
    __syncthreads();

    float* S = As;
    #pragma unroll
    for (int mt = 0; mt < 2; mt++)
        #pragma unroll
        for (int nt = 0; nt < 4; nt++) {
            int r = rbase + mt * 16 + g;
            int c = cbo + nt * 8 + t4 * 2;
            S[r * 72 + c]           = fmaxf(0.f, acc[mt][nt][0] + B1s[c]);
            S[r * 72 + c + 1]       = fmaxf(0.f, acc[mt][nt][1] + B1s[c + 1]);
            S[(r + 8) * 72 + c]     = fmaxf(0.f, acc[mt][nt][2] + B1s[c]);
            S[(r + 8) * 72 + c + 1] = fmaxf(0.f, acc[mt][nt][3] + B1s[c + 1]);
        }
    __syncthreads();
    {
        int r = tid >> 1, o = tid & 1;
        float s = 0.f;
        #pragma unroll
        for (int j = 0; j < 64; j++) s += S[r * 72 + j] * W2s[j * 2 + o];
        out[(tok0 + r) * 2 + o] = (s + b2[o]) * mask[tok0 + r];
    }
}

// ---------------- launch ----------------
extern "C" void kernel_launch(void* const* d_in, const int* in_sizes, int n_in,
                              void* d_out, int out_size) {
    const float* x     = (const float*)d_in[0];
    const float* mask  = (const float*)d_in[1];
    const float* emb_w = (const float*)d_in[2];
    const float* emb_b = (const float*)d_in[3];
    const float* lin_w = (const float*)d_in[4];
    const float* lin_b = (const float*)d_in[5];
    const float* nb_w  = (const float*)d_in[6];
    const float* nb_b  = (const float*)d_in[7];
    const float* bn_g  = (const float*)d_in[8];
    const float* bn_b  = (const float*)d_in[9];
    const float* o1w   = (const float*)d_in[10];
    const float* o1b   = (const float*)d_in[11];
    const float* o2w   = (const float*)d_in[12];
    const float* o2b   = (const float*)d_in[13];
    float* out = (float*)d_out;

    float *hA, *hB, *gP, *gQ;
    __half* wh;
    cudaGetSymbolAddress((void**)&hA, g_h);
    cudaGetSymbolAddress((void**)&hB, g_h2);
    cudaGetSymbolAddress((void**)&gP, g_gP);
    cudaGetSymbolAddress((void**)&gQ, g_gQ);
    cudaGetSymbolAddress((void**)&wh, g_wh);

    cudaFuncSetAttribute(gconv_kernel, cudaFuncAttributeMaxDynamicSharedMemorySize, GCONV_SMEM);
    cudaFuncSetAttribute(out_kernel,   cudaFuncAttributeMaxDynamicSharedMemorySize, OUT_SMEM);

    const int WSTR = 128 * 136;   // halves per matrix; layer l: lin at 2l, nb at 2l+1

    wprep_kernel<<<6, 256>>>(lin_w, nb_w);               // my launch 1
    emb_kernel<<<32768, 256>>>(x, emb_w, emb_b);         // 2
    pad_kernel<<<1, 32>>>();                             // 3
    pad_kernel<<<1, 32>>>();                             // 4
    // layer 0 — my launch 5, global slot 6 where ncu -s 5 lands
    gconv_kernel<<<2048, 512, GCONV_SMEM>>>(wh + 0 * WSTR, lin_b, nb_b, mask,
                                            hA, hA, hB, gP, 0);
    bnreduce_kernel<<<128, 256>>>(bn_g, bn_b);
    gconv_kernel<<<2048, 512, GCONV_SMEM>>>(wh + 2 * WSTR, lin_b + 128, nb_b + 128, mask,
                                            hA, gP, hB, gQ, 1);
    bnreduce_kernel<<<128, 256>>>(bn_g + 128, bn_b + 128);
    gconv_kernel<<<2048, 512, GCONV_SMEM>>>(wh + 4 * WSTR, lin_b + 256, nb_b + 256, mask,
                                            hB, gQ, hA, gP, 1);
    bnreduce_kernel<<<128, 256>>>(bn_g + 256, bn_b + 256);
    out_kernel<<<2048, 256, OUT_SMEM>>>(o1w, o1b, o2w, o2b, mask, out, hA, gP);
}

// round 7
// speedup vs baseline: 1.2856x; 1.0396x over previous
#include <cuda_runtime.h>
#include <cuda_fp16.h>
#include <cstdint>

#define TOK (32*8192)
#define NBATCH 8192
#define HD 128

// ---------------- scratch ----------------
__device__ __align__(16) float g_h [(size_t)TOK*HD];
__device__ __align__(16) float g_h2[(size_t)TOK*HD];
__device__ __align__(16) float g_gP[(size_t)TOK*HD];
__device__ __align__(16) float g_gQ[(size_t)TOK*HD];
__device__ __align__(16) float g_part[4096*256];
__device__ float g_sc[128];
__device__ float g_sh[128];
__device__ __align__(16) __half g_wh[6*128*136];   // [l][lin|nb] fp16, [n][k] stride 136

// ---------------- helpers ----------------
__device__ __forceinline__ float tf32r(float x) {
    uint32_t u;
    asm("cvt.rna.tf32.f32 %0, %1;" : "=r"(u) : "f"(x));
    return __uint_as_float(u);
}
__device__ __forceinline__ uint32_t fb(float x) { return __float_as_uint(x); }

__device__ __forceinline__ void mma16(float c[4], const uint32_t a[4], const uint32_t b[2]) {
    asm volatile(
        "mma.sync.aligned.m16n8k16.row.col.f32.f16.f16.f32 "
        "{%0,%1,%2,%3},{%4,%5,%6,%7},{%8,%9},{%0,%1,%2,%3};\n"
        : "+f"(c[0]), "+f"(c[1]), "+f"(c[2]), "+f"(c[3])
        : "r"(a[0]), "r"(a[1]), "r"(a[2]), "r"(a[3]), "r"(b[0]), "r"(b[1]));
}
__device__ __forceinline__ void mma8(float c[4], const uint32_t a[4], const uint32_t b[2]) {
    asm volatile(
        "mma.sync.aligned.m16n8k8.row.col.f32.tf32.tf32.f32 "
        "{%0,%1,%2,%3},{%4,%5,%6,%7},{%8,%9},{%0,%1,%2,%3};\n"
        : "+f"(c[0]), "+f"(c[1]), "+f"(c[2]), "+f"(c[3])
        : "r"(a[0]), "r"(a[1]), "r"(a[2]), "r"(a[3]), "r"(b[0]), "r"(b[1]));
}

__global__ void pad_kernel() {}

// ---------------- weight prep: [k][n] fp32 -> [n][k] fp16 (stride 136) ----------------
__global__ void wprep_kernel(const float* __restrict__ lw, const float* __restrict__ nw) {
    int m = blockIdx.x & 1, l = blockIdx.x >> 1;
    const float* src = (m ? nw : lw) + l * 16384;
    __half* dst = g_wh + blockIdx.x * (128 * 136);
    for (int idx = threadIdx.x; idx < 16384; idx += 256) {
        int k = idx >> 7, n = idx & 127;
        dst[n * 136 + k] = __float2half_rn(src[idx]);
    }
}

// ---------------- embedding ----------------
__global__ void emb_kernel(const float* __restrict__ x,
                           const float* __restrict__ ew,
                           const float* __restrict__ eb) {
    __shared__ float w0[128], w1[128], bb[128];
    if (threadIdx.x < 128) {
        w0[threadIdx.x] = ew[threadIdx.x];
        w1[threadIdx.x] = ew[128 + threadIdx.x];
        bb[threadIdx.x] = eb[threadIdx.x];
    }
    __syncthreads();
    size_t idx = (size_t)blockIdx.x * 256 + threadIdx.x;
    size_t t = idx >> 5;
    int c = (int)(idx & 31) << 2;
    float2 xv = *(const float2*)(x + t * 2);
    float4 o;
    o.x = xv.x * w0[c]   + xv.y * w1[c]   + bb[c];
    o.y = xv.x * w0[c+1] + xv.y * w1[c+1] + bb[c+1];
    o.z = xv.x * w0[c+2] + xv.y * w1[c+2] + bb[c+2];
    o.w = xv.x * w0[c+3] + xv.y * w1[c+3] + bb[c+3];
    *(float4*)(g_h + t * HD + c) = o;
}

// ---------------- gconv: fp16 HMMA, 64-row tiles, 2 CTA/SM ----------------
// smem bytes: Ah [66][136]h @0 (17952) | A2h [64][136]h @17952 (17408)
//             WLh @35360 (34816) | WNh @70176 (34816) | stats @104992 (2048)
// epilogue S fp32 [64][132] reuses @0
#define GCONV_SMEM 107040

__global__ __launch_bounds__(256, 2) void gconv_kernel(
    const __half* __restrict__ wimg,
    const float* __restrict__ lb, const float* __restrict__ nbb,
    const float* __restrict__ mask,
    const float* __restrict__ hin, const float* __restrict__ gin,
    float* __restrict__ hout, float* __restrict__ gout, int fuse)
{
    extern __shared__ char smc[];
    __half* Ah  = (__half*)smc;               // logical row lr at smem row lr+1
    __half* A2h = (__half*)(smc + 17952);
    __half* WLh = (__half*)(smc + 35360);
    __half* WNh = (__half*)(smc + 70176);
    float* ssum = (float*)(smc + 104992);
    float* ssq  = ssum + 128;
    float* scs  = ssq + 128;
    float* shs  = scs + 128;
    float* S    = (float*)smc;                // epilogue reuse [64][132]

    const int tid = threadIdx.x;
    const int bid = blockIdx.x;
    const int b = bid >> 7;                   // 128 CTAs per batch
    const int n_base = (bid & 127) << 6;      // *64
    const size_t tok0 = (size_t)b * NBATCH + n_base;

    if (tid < 128) {
        ssum[tid] = 0.f; ssq[tid] = 0.f;
        scs[tid] = g_sc[tid]; shs[tid] = g_sh[tid];
    }
    __syncthreads();

    // weights: straight uint4 copy of prepped fp16 images (2176 uint4 each)
    {
        const uint4* wl4 = (const uint4*)wimg;
        const uint4* wn4 = (const uint4*)(wimg + 128 * 136);
        uint4* WL4 = (uint4*)WLh;
        uint4* WN4 = (uint4*)WNh;
        for (int i = tid; i < 2176; i += 256) {
            WL4[i] = wl4[i];
            WN4[i] = wn4[i];
        }
    }
    // A tile with halo (66 rows); fused BN+ReLU+residual; store fp16
    for (int idx = tid; idx < 66 * 32; idx += 256) {
        int r = idx >> 5, c4 = (idx & 31) << 2;
        int lr = r - 1;
        int n = (n_base + lr) & (NBATCH - 1);
        size_t goff = ((size_t)b * NBATCH + n) * HD + c4;
        float4 v = *(const float4*)(hin + goff);
        if (fuse) {
            float4 gv = *(const float4*)(gin + goff);
            v.x += fmaxf(0.f, gv.x * scs[c4]     + shs[c4]);
            v.y += fmaxf(0.f, gv.y * scs[c4 + 1] + shs[c4 + 1]);
            v.z += fmaxf(0.f, gv.z * scs[c4 + 2] + shs[c4 + 2]);
            v.w += fmaxf(0.f, gv.w * scs[c4 + 3] + shs[c4 + 3]);
            if (lr >= 0 && lr < 64) *(float4*)(hout + goff) = v;
        }
        __half2 p0 = __floats2half2_rn(v.x, v.y);
        __half2 p1 = __floats2half2_rn(v.z, v.w);
        uint2 pk;
        pk.x = *(uint32_t*)&p0; pk.y = *(uint32_t*)&p1;
        *(uint2*)(Ah + r * 136 + c4) = pk;
    }
    __syncthreads();
    // A2 = neighbor sum (fp32-exact add of fp16 values, round once)
    {
        const uint32_t* AU = (const uint32_t*)Ah;
        uint32_t* A2U = (uint32_t*)A2h;
        for (int idx = tid; idx < 64 * 64; idx += 256) {
            int r = idx >> 6, j = idx & 63;
            uint32_t lo = AU[r * 68 + j];            // logical r-1 (smem row r)
            uint32_t hi = AU[(r + 2) * 68 + j];      // logical r+1
            float2 flo = __half22float2(*(__half2*)&lo);
            float2 fhi = __half22float2(*(__half2*)&hi);
            __half2 sres = __floats2half2_rn(flo.x + fhi.x, flo.y + fhi.y);
            A2U[r * 68 + j] = *(uint32_t*)&sres;
        }
    }
    __syncthreads();

    const int w = tid >> 5, lane = tid & 31;
    const int g = lane >> 2, t4 = lane & 3;
    const int wm = w & 1, wn = w >> 1;        // 2 m x 4 n warp grid
    const bool isR = (wn >= 2);
    const int rbase = wm * 32;
    const int cb = (wn & 1) * 64;

    const uint32_t* AU  = (const uint32_t*)(isR ? A2h : Ah);
    const uint32_t* WU  = (const uint32_t*)(isR ? WNh : WLh);
    const int rowadd = isR ? 0 : 68;          // Ah logical row r at smem row r+1

    float acc[2][8][4];
    #pragma unroll
    for (int i = 0; i < 2; i++)
        #pragma unroll
        for (int j = 0; j < 8; j++)
            #pragma unroll
            for (int q = 0; q < 4; q++) acc[i][j][q] = 0.f;

    #pragma unroll
    for (int ks = 0; ks < 8; ks++) {
        const int k2 = ks * 8;
        uint32_t afr[2][4];
        #pragma unroll
        for (int mt = 0; mt < 2; mt++) {
            const uint32_t* p = AU + (rbase + mt * 16 + g) * 68 + rowadd + k2 + t4;
            afr[mt][0] = p[0];
            afr[mt][1] = p[8 * 68];
            afr[mt][2] = p[4];
            afr[mt][3] = p[8 * 68 + 4];
        }
        uint32_t bfr[8][2];
        #pragma unroll
        for (int nt = 0; nt < 8; nt++) {
            const uint32_t* p = WU + (cb + nt * 8 + g) * 68 + k2 + t4;
            bfr[nt][0] = p[0];
            bfr[nt][1] = p[4];
        }
        #pragma unroll
        for (int mt = 0; mt < 2; mt++)
            #pragma unroll
            for (int nt = 0; nt < 8; nt++)
                mma16(acc[mt][nt], afr[mt], bfr[nt]);
    }

    __syncthreads();     // all smem fp16 reads done; S may overwrite

    if (isR) {
        #pragma unroll
        for (int mt = 0; mt < 2; mt++)
            #pragma unroll
            for (int nt = 0; nt < 8; nt++) {
                int r = rbase + mt * 16 + g;
                int c = cb + nt * 8 + t4 * 2;
                S[r * 132 + c]           = acc[mt][nt][0];
                S[r * 132 + c + 1]       = acc[mt][nt][1];
                S[(r + 8) * 132 + c]     = acc[mt][nt][2];
                S[(r + 8) * 132 + c + 1] = acc[mt][nt][3];
            }
    }
    __syncthreads();
    if (!isR) {
        #pragma unroll
        for (int mt = 0; mt < 2; mt++) {
            int r = rbase + mt * 16 + g;
            float m0 = mask[tok0 + r];
            float m1 = mask[tok0 + r + 8];
            #pragma unroll
            for (int nt = 0; nt < 8; nt++) {
                int c = cb + nt * 8 + t4 * 2;
                float bia0 = lb[c] + nbb[c];
                float bia1 = lb[c + 1] + nbb[c + 1];
                S[r * 132 + c]           = (acc[mt][nt][0] + S[r * 132 + c]           + bia0) * m0;
                S[r * 132 + c + 1]       = (acc[mt][nt][1] + S[r * 132 + c + 1]       + bia1) * m0;
                S[(r + 8) * 132 + c]     = (acc[mt][nt][2] + S[(r + 8) * 132 + c]     + bia0) * m1;
                S[(r + 8) * 132 + c + 1] = (acc[mt][nt][3] + S[(r + 8) * 132 + c + 1] + bia1) * m1;
            }
        }
    }
    __syncthreads();

    {
        int c = tid & 127, seg = tid >> 7;    // 2 segs x 32 rows
        float s = 0.f, q = 0.f;
        #pragma unroll 8
        for (int r = seg * 32; r < seg * 32 + 32; r++) {
            float v = S[r * 132 + c];
            s += v; q += v * v;
        }
        atomicAdd(&ssum[c], s);
        atomicAdd(&ssq[c], q);
    }
    for (int idx = tid; idx < 64 * 32; idx += 256) {
        int r = idx >> 5, c4 = (idx & 31) << 2;
        float4 v = *(const float4*)(S + r * 132 + c4);
        *(float4*)(gout + (tok0 + r) * HD + c4) = v;
    }
    __syncthreads();
    if (tid < 256) g_part[bid * 256 + tid] = (tid < 128) ? ssum[tid] : ssq[tid - 128];
}

// ---------------- BN reduce (4096 partials) ----------------
__global__ void bnreduce_kernel(const float* __restrict__ gam, const float* __restrict__ bet) {
    __shared__ float rs[256], rq[256];
    int c = blockIdx.x, tid = threadIdx.x;
    float s = 0.f, q = 0.f;
    #pragma unroll
    for (int i = 0; i < 16; i++) {
        int cta = tid * 16 + i;
        s += g_part[cta * 256 + c];
        q += g_part[cta * 256 + 128 + c];
    }
    rs[tid] = s; rq[tid] = q;
    __syncthreads();
    for (int o = 128; o > 0; o >>= 1) {
        if (tid < o) { rs[tid] += rs[tid + o]; rq[tid] += rq[tid + o]; }
        __syncthreads();
    }
    if (tid == 0) {
        float inv = 1.f / (float)TOK;
        float mean = rs[0] * inv;
        float var = rq[0] * inv - mean * mean;
        float sc = gam[c] * rsqrtf(var + 1e-5f);
        g_sc[c] = sc;
        g_sh[c] = bet[c] - mean * sc;
    }
}

// ---------------- output head (fused final BN), tf32 mma ----------------
#define AS2_ELEMS (128*132)
#define W1S_ELEMS (128*72)
#define OUT_SMEM ((AS2_ELEMS + W1S_ELEMS + 128 + 64 + 256) * 4)

__global__ __launch_bounds__(256, 1) void out_kernel(
    const float* __restrict__ w1, const float* __restrict__ b1,
    const float* __restrict__ w2, const float* __restrict__ b2,
    const float* __restrict__ mask, float* __restrict__ out,
    const float* __restrict__ hin, const float* __restrict__ gin)
{
    extern __shared__ float sm[];
    float* As  = sm;
    float* W1s = As + AS2_ELEMS;
    float* W2s = W1s + W1S_ELEMS;
    float* B1s = W2s + 128;
    float* scs = B1s + 64;
    float* shs = scs + 128;
    const int tid = threadIdx.x, bid = blockIdx.x;
    const size_t tok0 = (size_t)bid * 128;

    if (tid < 128) { scs[tid] = g_sc[tid]; shs[tid] = g_sh[tid]; W2s[tid] = w2[tid]; }
    if (tid < 64)  B1s[tid] = b1[tid];
    __syncthreads();

    for (int idx = tid; idx < 128 * 32; idx += 256) {
        int r = idx >> 5, c4 = (idx & 31) << 2;
        size_t goff = (tok0 + r) * HD + c4;
        float4 hv = *(const float4*)(hin + goff);
        float4 gv = *(const float4*)(gin + goff);
        float* d = As + r * 132 + c4;
        d[0] = tf32r(hv.x + fmaxf(0.f, gv.x * scs[c4]     + shs[c4]));
        d[1] = tf32r(hv.y + fmaxf(0.f, gv.y * scs[c4 + 1] + shs[c4 + 1]));
        d[2] = tf32r(hv.z + fmaxf(0.f, gv.z * scs[c4 + 2] + shs[c4 + 2]));
        d[3] = tf32r(hv.w + fmaxf(0.f, gv.w * scs[c4 + 3] + shs[c4 + 3]));
    }
    for (int idx = tid; idx < 128 * 16; idx += 256) {
        int k = idx >> 4, c4 = (idx & 15) << 2;
        float4 v = *(const float4*)(w1 + k * 64 + c4);
        float* d = W1s + k * 72 + c4;
        d[0] = tf32r(v.x); d[1] = tf32r(v.y); d[2] = tf32r(v.z); d[3] = tf32r(v.w);
    }
    __syncthreads();

    const int w = tid >> 5, lane = tid & 31, g = lane >> 2, t4 = lane & 3;
    const int wm = w & 3, wn = w >> 2;
    const int rbase = wm * 32, cbo = wn * 32;

    float acc[2][4][4];
    #pragma unroll
    for (int i = 0; i < 2; i++)
        #pragma unroll
        for (int j = 0; j < 4; j++)
            #pragma unroll
            for (int q = 0; q < 4; q++) acc[i][j][q] = 0.f;

    for (int k0 = 0; k0 < 128; k0 += 8) {
        uint32_t afr[2][4];
        #pragma unroll
        for (int mt = 0; mt < 2; mt++) {
            const float* p = As + (rbase + mt * 16 + g) * 132 + k0 + t4;
            afr[mt][0] = fb(p[0]);
            afr[mt][1] = fb(p[8 * 132]);
            afr[mt][2] = fb(p[4]);
            afr[mt][3] = fb(p[8 * 132 + 4]);
        }
        uint32_t bfr[4][2];
        #pragma unroll
        for (int nt = 0; nt < 4; nt++) {
            const float* p = W1s + (k0 + t4) * 72 + cbo + nt * 8 + g;
            bfr[nt][0] = fb(p[0]);
            bfr[nt][1] = fb(p[4 * 72]);
        }
        #pragma unroll
        for (int mt = 0; mt < 2; mt++)
            #pragma unroll
            for (int nt = 0; nt < 4; nt++)
                mma8(acc[mt][nt], afr[mt], bfr[nt]);
    }
    __syncthreads();

    float* S = As;
    #pragma unroll
    for (int mt = 0; mt < 2; mt++)
        #pragma unroll
        for (int nt = 0; nt < 4; nt++) {
            int r = rbase + mt * 16 + g;
            int c = cbo + nt * 8 + t4 * 2;
            S[r * 72 + c]           = fmaxf(0.f, acc[mt][nt][0] + B1s[c]);
            S[r * 72 + c + 1]       = fmaxf(0.f, acc[mt][nt][1] + B1s[c + 1]);
            S[(r + 8) * 72 + c]     = fmaxf(0.f, acc[mt][nt][2] + B1s[c]);
            S[(r + 8) * 72 + c + 1] = fmaxf(0.f, acc[mt][nt][3] + B1s[c + 1]);
        }
    __syncthreads();
    {
        int r = tid >> 1, o = tid & 1;
        float s = 0.f;
        #pragma unroll
        for (int j = 0; j < 64; j++) s += S[r * 72 + j] * W2s[j * 2 + o];
        out[(tok0 + r) * 2 + o] = (s + b2[o]) * mask[tok0 + r];
    }
}

// ---------------- launch ----------------
extern "C" void kernel_launch(void* const* d_in, const int* in_sizes, int n_in,
                              void* d_out, int out_size) {
    const float* x     = (const float*)d_in[0];
    const float* mask  = (const float*)d_in[1];
    const float* emb_w = (const float*)d_in[2];
    const float* emb_b = (const float*)d_in[3];
    const float* lin_w = (const float*)d_in[4];
    const float* lin_b = (const float*)d_in[5];
    const float* nb_w  = (const float*)d_in[6];
    const float* nb_b  = (const float*)d_in[7];
    const float* bn_g  = (const float*)d_in[8];
    const float* bn_b  = (const float*)d_in[9];
    const float* o1w   = (const float*)d_in[10];
    const float* o1b   = (const float*)d_in[11];
    const float* o2w   = (const float*)d_in[12];
    const float* o2b   = (const float*)d_in[13];
    float* out = (float*)d_out;

    float *hA, *hB, *gP, *gQ;
    __half* wh;
    cudaGetSymbolAddress((void**)&hA, g_h);
    cudaGetSymbolAddress((void**)&hB, g_h2);
    cudaGetSymbolAddress((void**)&gP, g_gP);
    cudaGetSymbolAddress((void**)&gQ, g_gQ);
    cudaGetSymbolAddress((void**)&wh, g_wh);

    cudaFuncSetAttribute(gconv_kernel, cudaFuncAttributeMaxDynamicSharedMemorySize, GCONV_SMEM);
    cudaFuncSetAttribute(out_kernel,   cudaFuncAttributeMaxDynamicSharedMemorySize, OUT_SMEM);

    const int WSTR = 128 * 136;   // halves per matrix; layer l: lin at 2l, nb at 2l+1

    wprep_kernel<<<6, 256>>>(lin_w, nb_w);               // my launch 1 (global 3)
    emb_kernel<<<32768, 256>>>(x, emb_w, emb_b);         // 2 (global 4)
    pad_kernel<<<1, 32>>>();                             // 3 (global 5)
    // layer 0 — my launch 4, global slot 6 where ncu -s 5 lands
    gconv_kernel<<<4096, 256, GCONV_SMEM>>>(wh + 0 * WSTR, lin_b, nb_b, mask,
                                            hA, hA, hB, gP, 0);
    bnreduce_kernel<<<128, 256>>>(bn_g, bn_b);
    gconv_kernel<<<4096, 256, GCONV_SMEM>>>(wh + 2 * WSTR, lin_b + 128, nb_b + 128, mask,
                                            hA, gP, hB, gQ, 1);
    bnreduce_kernel<<<128, 256>>>(bn_g + 128, bn_b + 128);
    gconv_kernel<<<4096, 256, GCONV_SMEM>>>(wh + 4 * WSTR, lin_b + 256, nb_b + 256, mask,
                                            hB, gQ, hA, gP, 1);
    bnreduce_kernel<<<128, 256>>>(bn_g + 256, bn_b + 256);
    out_kernel<<<2048, 256, OUT_SMEM>>>(o1w, o1b, o2w, o2b, mask, out, hA, gP);
}

// round 8
// speedup vs baseline: 1.6302x; 1.2681x over previous
#include <cuda_runtime.h>
#include <cuda_fp16.h>
#include <cstdint>

#define TOK (32*8192)
#define NBATCH 8192
#define HD 128
#define GGRID 304   // persistent gconv grid (2 per SM on 152 SMs)
#define NTILES 4096

// ---------------- scratch ----------------
__device__ __align__(16) float g_h [(size_t)TOK*HD];
__device__ __align__(16) float g_h2[(size_t)TOK*HD];
__device__ __align__(16) float g_gP[(size_t)TOK*HD];
__device__ __align__(16) float g_gQ[(size_t)TOK*HD];
__device__ __align__(16) float g_part[GGRID*256];
__device__ float g_sc[128];
__device__ float g_sh[128];
__device__ __align__(16) __half g_wh[6*128*136];   // [l][lin|nb] fp16, [n][k] stride 136

// ---------------- helpers ----------------
__device__ __forceinline__ float tf32r(float x) {
    uint32_t u;
    asm("cvt.rna.tf32.f32 %0, %1;" : "=r"(u) : "f"(x));
    return __uint_as_float(u);
}
__device__ __forceinline__ uint32_t fb(float x) { return __float_as_uint(x); }

__device__ __forceinline__ void mma16(float c[4], const uint32_t a[4], const uint32_t b[2]) {
    asm volatile(
        "mma.sync.aligned.m16n8k16.row.col.f32.f16.f16.f32 "
        "{%0,%1,%2,%3},{%4,%5,%6,%7},{%8,%9},{%0,%1,%2,%3};\n"
        : "+f"(c[0]), "+f"(c[1]), "+f"(c[2]), "+f"(c[3])
        : "r"(a[0]), "r"(a[1]), "r"(a[2]), "r"(a[3]), "r"(b[0]), "r"(b[1]));
}
__device__ __forceinline__ void mma8(float c[4], const uint32_t a[4], const uint32_t b[2]) {
    asm volatile(
        "mma.sync.aligned.m16n8k8.row.col.f32.tf32.tf32.f32 "
        "{%0,%1,%2,%3},{%4,%5,%6,%7},{%8,%9},{%0,%1,%2,%3};\n"
        : "+f"(c[0]), "+f"(c[1]), "+f"(c[2]), "+f"(c[3])
        : "r"(a[0]), "r"(a[1]), "r"(a[2]), "r"(a[3]), "r"(b[0]), "r"(b[1]));
}

__global__ void pad_kernel() {}

// ---------------- weight prep: [k][n] fp32 -> [n][k] fp16 (stride 136) ----------------
__global__ void wprep_kernel(const float* __restrict__ lw, const float* __restrict__ nw) {
    int m = blockIdx.x & 1, l = blockIdx.x >> 1;
    const float* src = (m ? nw : lw) + l * 16384;
    __half* dst = g_wh + blockIdx.x * (128 * 136);
    for (int idx = threadIdx.x; idx < 16384; idx += 256) {
        int k = idx >> 7, n = idx & 127;
        dst[n * 136 + k] = __float2half_rn(src[idx]);
    }
}

// ---------------- embedding ----------------
__global__ void emb_kernel(const float* __restrict__ x,
                           const float* __restrict__ ew,
                           const float* __restrict__ eb) {
    __shared__ float w0[128], w1[128], bb[128];
    if (threadIdx.x < 128) {
        w0[threadIdx.x] = ew[threadIdx.x];
        w1[threadIdx.x] = ew[128 + threadIdx.x];
        bb[threadIdx.x] = eb[threadIdx.x];
    }
    __syncthreads();
    size_t idx = (size_t)blockIdx.x * 256 + threadIdx.x;
    size_t t = idx >> 5;
    int c = (int)(idx & 31) << 2;
    float2 xv = *(const float2*)(x + t * 2);
    float4 o;
    o.x = xv.x * w0[c]   + xv.y * w1[c]   + bb[c];
    o.y = xv.x * w0[c+1] + xv.y * w1[c+1] + bb[c+1];
    o.z = xv.x * w0[c+2] + xv.y * w1[c+2] + bb[c+2];
    o.w = xv.x * w0[c+3] + xv.y * w1[c+3] + bb[c+3];
    *(float4*)(g_h + t * HD + c) = o;
}

// ---------------- gconv: persistent multi-tile, fp16 HMMA, 2 CTA/SM ----------------
// smem bytes: Ah [66][136]h @0 (17952) | A2h [64][136]h @17952 (17408)
//             WLh @35360 (34816) | WNh @70176 (34816) | stats @104992 (2048)
// epilogue S fp32 [64][132] reuses @0
#define GCONV_SMEM 107040

__global__ __launch_bounds__(256, 2) void gconv_kernel(
    const __half* __restrict__ wimg,
    const float* __restrict__ lb, const float* __restrict__ nbb,
    const float* __restrict__ mask,
    const float* __restrict__ hin, const float* __restrict__ gin,
    float* __restrict__ hout, float* __restrict__ gout, int fuse)
{
    extern __shared__ char smc[];
    __half* Ah  = (__half*)smc;               // logical row lr at smem row lr+1
    __half* A2h = (__half*)(smc + 17952);
    __half* WLh = (__half*)(smc + 35360);
    __half* WNh = (__half*)(smc + 70176);
    float* ssum = (float*)(smc + 104992);
    float* ssq  = ssum + 128;
    float* scs  = ssq + 128;
    float* shs  = scs + 128;
    float* S    = (float*)smc;                // epilogue reuse [64][132]

    const int tid = threadIdx.x;
    const int bid = blockIdx.x;

    if (tid < 128) {
        ssum[tid] = 0.f; ssq[tid] = 0.f;
        scs[tid] = g_sc[tid]; shs[tid] = g_sh[tid];
    }
    // weights: once per persistent CTA
    {
        const uint4* wl4 = (const uint4*)wimg;
        const uint4* wn4 = (const uint4*)(wimg + 128 * 136);
        uint4* WL4 = (uint4*)WLh;
        uint4* WN4 = (uint4*)WNh;
        for (int i = tid; i < 2176; i += 256) {
            WL4[i] = wl4[i];
            WN4[i] = wn4[i];
        }
    }

    // per-warp constants
    const int w = tid >> 5, lane = tid & 31;
    const int g = lane >> 2, t4 = lane & 3;
    const int wm = w & 1, wn = w >> 1;        // 2 m x 4 n warp grid
    const bool isR = (wn >= 2);
    const int rbase = wm * 32;
    const int cb = (wn & 1) * 64;
    const uint32_t* AU  = (const uint32_t*)(isR ? A2h : Ah);
    const uint32_t* WU  = (const uint32_t*)(isR ? WNh : WLh);
    const int rowadd = isR ? 0 : 68;          // Ah logical row r at smem row r+1

    for (int t = bid; t < NTILES; t += GGRID) {
        const int b = t >> 7;                 // 128 tiles per batch
        const int n_base = (t & 127) << 6;    // *64
        const size_t tok0 = (size_t)b * NBATCH + n_base;

        __syncthreads();   // S/Ah reuse + stats from previous tile done

        // A tile with halo (66 rows); fused BN+ReLU+residual; store fp16
        for (int idx = tid; idx < 66 * 32; idx += 256) {
            int r = idx >> 5, c4 = (idx & 31) << 2;
            int lr = r - 1;
            int n = (n_base + lr) & (NBATCH - 1);
            size_t goff = ((size_t)b * NBATCH + n) * HD + c4;
            float4 v = *(const float4*)(hin + goff);
            if (fuse) {
                float4 gv = *(const float4*)(gin + goff);
                v.x += fmaxf(0.f, gv.x * scs[c4]     + shs[c4]);
                v.y += fmaxf(0.f, gv.y * scs[c4 + 1] + shs[c4 + 1]);
                v.z += fmaxf(0.f, gv.z * scs[c4 + 2] + shs[c4 + 2]);
                v.w += fmaxf(0.f, gv.w * scs[c4 + 3] + shs[c4 + 3]);
                if (lr >= 0 && lr < 64) *(float4*)(hout + goff) = v;
            }
            __half2 p0 = __floats2half2_rn(v.x, v.y);
            __half2 p1 = __floats2half2_rn(v.z, v.w);
            uint2 pk;
            pk.x = *(uint32_t*)&p0; pk.y = *(uint32_t*)&p1;
            *(uint2*)(Ah + r * 136 + c4) = pk;
        }
        __syncthreads();
        // A2 = neighbor sum
        {
            const uint32_t* AUl = (const uint32_t*)Ah;
            uint32_t* A2U = (uint32_t*)A2h;
            for (int idx = tid; idx < 64 * 64; idx += 256) {
                int r = idx >> 6, j = idx & 63;
                uint32_t lo = AUl[r * 68 + j];
                uint32_t hi = AUl[(r + 2) * 68 + j];
                float2 flo = __half22float2(*(__half2*)&lo);
                float2 fhi = __half22float2(*(__half2*)&hi);
                __half2 sres = __floats2half2_rn(flo.x + fhi.x, flo.y + fhi.y);
                A2U[r * 68 + j] = *(uint32_t*)&sres;
            }
        }
        __syncthreads();

        float acc[2][8][4];
        #pragma unroll
        for (int i = 0; i < 2; i++)
            #pragma unroll
            for (int j = 0; j < 8; j++)
                #pragma unroll
                for (int q = 0; q < 4; q++) acc[i][j][q] = 0.f;

        #pragma unroll
        for (int ks = 0; ks < 8; ks++) {
            const int k2 = ks * 8;
            uint32_t afr[2][4];
            #pragma unroll
            for (int mt = 0; mt < 2; mt++) {
                const uint32_t* p = AU + (rbase + mt * 16 + g) * 68 + rowadd + k2 + t4;
                afr[mt][0] = p[0];
                afr[mt][1] = p[8 * 68];
                afr[mt][2] = p[4];
                afr[mt][3] = p[8 * 68 + 4];
            }
            uint32_t bfr[8][2];
            #pragma unroll
            for (int nt = 0; nt < 8; nt++) {
                const uint32_t* p = WU + (cb + nt * 8 + g) * 68 + k2 + t4;
                bfr[nt][0] = p[0];
                bfr[nt][1] = p[4];
            }
            #pragma unroll
            for (int mt = 0; mt < 2; mt++)
                #pragma unroll
                for (int nt = 0; nt < 8; nt++)
                    mma16(acc[mt][nt], afr[mt], bfr[nt]);
        }

        __syncthreads();     // fp16 A reads done; S may overwrite

        if (isR) {
            #pragma unroll
            for (int mt = 0; mt < 2; mt++)
                #pragma unroll
                for (int nt = 0; nt < 8; nt++) {
                    int r = rbase + mt * 16 + g;
                    int c = cb + nt * 8 + t4 * 2;
                    S[r * 132 + c]           = acc[mt][nt][0];
                    S[r * 132 + c + 1]       = acc[mt][nt][1];
                    S[(r + 8) * 132 + c]     = acc[mt][nt][2];
                    S[(r + 8) * 132 + c + 1] = acc[mt][nt][3];
                }
        }
        __syncthreads();
        if (!isR) {
            #pragma unroll
            for (int mt = 0; mt < 2; mt++) {
                int r = rbase + mt * 16 + g;
                float m0 = mask[tok0 + r];
                float m1 = mask[tok0 + r + 8];
                #pragma unroll
                for (int nt = 0; nt < 8; nt++) {
                    int c = cb + nt * 8 + t4 * 2;
                    float bia0 = lb[c] + nbb[c];
                    float bia1 = lb[c + 1] + nbb[c + 1];
                    S[r * 132 + c]           = (acc[mt][nt][0] + S[r * 132 + c]           + bia0) * m0;
                    S[r * 132 + c + 1]       = (acc[mt][nt][1] + S[r * 132 + c + 1]       + bia1) * m0;
                    S[(r + 8) * 132 + c]     = (acc[mt][nt][2] + S[(r + 8) * 132 + c]     + bia0) * m1;
                    S[(r + 8) * 132 + c + 1] = (acc[mt][nt][3] + S[(r + 8) * 132 + c + 1] + bia1) * m1;
                }
            }
        }
        __syncthreads();

        // stats accumulate across tiles; store G
        {
            int c = tid & 127, seg = tid >> 7;
            float s = 0.f, q = 0.f;
            #pragma unroll 8
            for (int r = seg * 32; r < seg * 32 + 32; r++) {
                float v = S[r * 132 + c];
                s += v; q += v * v;
            }
            atomicAdd(&ssum[c], s);
            atomicAdd(&ssq[c], q);
        }
        for (int idx = tid; idx < 64 * 32; idx += 256) {
            int r = idx >> 5, c4 = (idx & 31) << 2;
            float4 v = *(const float4*)(S + r * 132 + c4);
            *(float4*)(gout + (tok0 + r) * HD + c4) = v;
        }
    }
    __syncthreads();
    if (tid < 256) g_part[bid * 256 + tid] = (tid < 128) ? ssum[tid] : ssq[tid - 128];
}

// ---------------- BN reduce (GGRID partials) ----------------
__global__ void bnreduce_kernel(const float* __restrict__ gam, const float* __restrict__ bet) {
    __shared__ float rs[256], rq[256];
    int c = blockIdx.x, tid = threadIdx.x;
    float s = 0.f, q = 0.f;
    for (int i = tid; i < GGRID; i += 256) {
        s += g_part[i * 256 + c];
        q += g_part[i * 256 + 128 + c];
    }
    rs[tid] = s; rq[tid] = q;
    __syncthreads();
    for (int o = 128; o > 0; o >>= 1) {
        if (tid < o) { rs[tid] += rs[tid + o]; rq[tid] += rq[tid + o]; }
        __syncthreads();
    }
    if (tid == 0) {
        float inv = 1.f / (float)TOK;
        float mean = rs[0] * inv;
        float var = rq[0] * inv - mean * mean;
        float sc = gam[c] * rsqrtf(var + 1e-5f);
        g_sc[c] = sc;
        g_sh[c] = bet[c] - mean * sc;
    }
}

// ---------------- output head (fused final BN), tf32 mma ----------------
#define AS2_ELEMS (128*132)
#define W1S_ELEMS (128*72)
#define OUT_SMEM ((AS2_ELEMS + W1S_ELEMS + 128 + 64 + 256) * 4)

__global__ __launch_bounds__(256, 1) void out_kernel(
    const float* __restrict__ w1, const float* __restrict__ b1,
    const float* __restrict__ w2, const float* __restrict__ b2,
    const float* __restrict__ mask, float* __restrict__ out,
    const float* __restrict__ hin, const float* __restrict__ gin)
{
    extern __shared__ float sm[];
    float* As  = sm;
    float* W1s = As + AS2_ELEMS;
    float* W2s = W1s + W1S_ELEMS;
    float* B1s = W2s + 128;
    float* scs = B1s + 64;
    float* shs = scs + 128;
    const int tid = threadIdx.x, bid = blockIdx.x;
    const size_t tok0 = (size_t)bid * 128;

    if (tid < 128) { scs[tid] = g_sc[tid]; shs[tid] = g_sh[tid]; W2s[tid] = w2[tid]; }
    if (tid < 64)  B1s[tid] = b1[tid];
    __syncthreads();

    for (int idx = tid; idx < 128 * 32; idx += 256) {
        int r = idx >> 5, c4 = (idx & 31) << 2;
        size_t goff = (tok0 + r) * HD + c4;
        float4 hv = *(const float4*)(hin + goff);
        float4 gv = *(const float4*)(gin + goff);
        float* d = As + r * 132 + c4;
        d[0] = tf32r(hv.x + fmaxf(0.f, gv.x * scs[c4]     + shs[c4]));
        d[1] = tf32r(hv.y + fmaxf(0.f, gv.y * scs[c4 + 1] + shs[c4 + 1]));
        d[2] = tf32r(hv.z + fmaxf(0.f, gv.z * scs[c4 + 2] + shs[c4 + 2]));
        d[3] = tf32r(hv.w + fmaxf(0.f, gv.w * scs[c4 + 3] + shs[c4 + 3]));
    }
    for (int idx = tid; idx < 128 * 16; idx += 256) {
        int k = idx >> 4, c4 = (idx & 15) << 2;
        float4 v = *(const float4*)(w1 + k * 64 + c4);
        float* d = W1s + k * 72 + c4;
        d[0] = tf32r(v.x); d[1] = tf32r(v.y); d[2] = tf32r(v.z); d[3] = tf32r(v.w);
    }
    __syncthreads();

    const int w = tid >> 5, lane = tid & 31, g = lane >> 2, t4 = lane & 3;
    const int wm = w & 3, wn = w >> 2;
    const int rbase = wm * 32, cbo = wn * 32;

    float acc[2][4][4];
    #pragma unroll
    for (int i = 0; i < 2; i++)
        #pragma unroll
        for (int j = 0; j < 4; j++)
            #pragma unroll
            for (int q = 0; q < 4; q++) acc[i][j][q] = 0.f;

    for (int k0 = 0; k0 < 128; k0 += 8) {
        uint32_t afr[2][4];
        #pragma unroll
        for (int mt = 0; mt < 2; mt++) {
            const float* p = As + (rbase + mt * 16 + g) * 132 + k0 + t4;
            afr[mt][0] = fb(p[0]);
            afr[mt][1] = fb(p[8 * 132]);
            afr[mt][2] = fb(p[4]);
            afr[mt][3] = fb(p[8 * 132 + 4]);
        }
        uint32_t bfr[4][2];
        #pragma unroll
        for (int nt = 0; nt < 4; nt++) {
            const float* p = W1s + (k0 + t4) * 72 + cbo + nt * 8 + g;
            bfr[nt][0] = fb(p[0]);
            bfr[nt][1] = fb(p[4 * 72]);
        }
        #pragma unroll
        for (int mt = 0; mt < 2; mt++)
            #pragma unroll
            for (int nt = 0; nt < 4; nt++)
                mma8(acc[mt][nt], afr[mt], bfr[nt]);
    }
    __syncthreads();

    float* S = As;
    #pragma unroll
    for (int mt = 0; mt < 2; mt++)
        #pragma unroll
        for (int nt = 0; nt < 4; nt++) {
            int r = rbase + mt * 16 + g;
            int c = cbo + nt * 8 + t4 * 2;
            S[r * 72 + c]           = fmaxf(0.f, acc[mt][nt][0] + B1s[c]);
            S[r * 72 + c + 1]       = fmaxf(0.f, acc[mt][nt][1] + B1s[c + 1]);
            S[(r + 8) * 72 + c]     = fmaxf(0.f, acc[mt][nt][2] + B1s[c]);
            S[(r + 8) * 72 + c + 1] = fmaxf(0.f, acc[mt][nt][3] + B1s[c + 1]);
        }
    __syncthreads();
    {
        int r = tid >> 1, o = tid & 1;
        float s = 0.f;
        #pragma unroll
        for (int j = 0; j < 64; j++) s += S[r * 72 + j] * W2s[j * 2 + o];
        out[(tok0 + r) * 2 + o] = (s + b2[o]) * mask[tok0 + r];
    }
}

// ---------------- launch ----------------
extern "C" void kernel_launch(void* const* d_in, const int* in_sizes, int n_in,
                              void* d_out, int out_size) {
    const float* x     = (const float*)d_in[0];
    const float* mask  = (const float*)d_in[1];
    const float* emb_w = (const float*)d_in[2];
    const float* emb_b = (const float*)d_in[3];
    const float* lin_w = (const float*)d_in[4];
    const float* lin_b = (const float*)d_in[5];
    const float* nb_w  = (const float*)d_in[6];
    const float* nb_b  = (const float*)d_in[7];
    const float* bn_g  = (const float*)d_in[8];
    const float* bn_b  = (const float*)d_in[9];
    const float* o1w   = (const float*)d_in[10];
    const float* o1b   = (const float*)d_in[11];
    const float* o2w   = (const float*)d_in[12];
    const float* o2b   = (const float*)d_in[13];
    float* out = (float*)d_out;

    float *hA, *hB, *gP, *gQ;
    __half* wh;
    cudaGetSymbolAddress((void**)&hA, g_h);
    cudaGetSymbolAddress((void**)&hB, g_h2);
    cudaGetSymbolAddress((void**)&gP, g_gP);
    cudaGetSymbolAddress((void**)&gQ, g_gQ);
    cudaGetSymbolAddress((void**)&wh, g_wh);

    cudaFuncSetAttribute(gconv_kernel, cudaFuncAttributeMaxDynamicSharedMemorySize, GCONV_SMEM);
    cudaFuncSetAttribute(out_kernel,   cudaFuncAttributeMaxDynamicSharedMemorySize, OUT_SMEM);

    const int WSTR = 128 * 136;   // halves per matrix; layer l: lin at 2l, nb at 2l+1

    wprep_kernel<<<6, 256>>>(lin_w, nb_w);               // my launch 1 (global 3)
    emb_kernel<<<32768, 256>>>(x, emb_w, emb_b);         // 2 (global 4)
    pad_kernel<<<1, 32>>>();                             // 3 (global 5)
    // layer 0 — my launch 4, global slot 6 where ncu -s 5 lands
    gconv_kernel<<<GGRID, 256, GCONV_SMEM>>>(wh + 0 * WSTR, lin_b, nb_b, mask,
                                             hA, hA, hB, gP, 0);
    bnreduce_kernel<<<128, 256>>>(bn_g, bn_b);
    gconv_kernel<<<GGRID, 256, GCONV_SMEM>>>(wh + 2 * WSTR, lin_b + 128, nb_b + 128, mask,
                                             hA, gP, hB, gQ, 1);
    bnreduce_kernel<<<128, 256>>>(bn_g + 128, bn_b + 128);
    gconv_kernel<<<GGRID, 256, GCONV_SMEM>>>(wh + 4 * WSTR, lin_b + 256, nb_b + 256, mask,
                                             hB, gQ, hA, gP, 1);
    bnreduce_kernel<<<128, 256>>>(bn_g + 256, bn_b + 256);
    out_kernel<<<2048, 256, OUT_SMEM>>>(o1w, o1b, o2w, o2b, mask, out, hA, gP);
}

// round 9
// speedup vs baseline: 1.8348x; 1.1255x over previous
#include <cuda_runtime.h>
#include <cuda_fp16.h>
#include <cstdint>

#define TOK (32*8192)
#define NBATCH 8192
#define HD 128
#define GGRID 304   // persistent grid (2 per SM on 152 SMs)
#define NTILES 4096

// ---------------- scratch ----------------
__device__ __align__(16) float g_h [(size_t)TOK*HD];
__device__ __align__(16) float g_h2[(size_t)TOK*HD];
__device__ __align__(16) float g_gP[(size_t)TOK*HD];
__device__ __align__(16) float g_gQ[(size_t)TOK*HD];
__device__ __align__(16) float g_part[GGRID*256];
__device__ float g_sc[128];
__device__ float g_sh[128];
__device__ __align__(16) __half g_wh[6*128*136];   // gconv weights fp16, [n][k] stride 136
__device__ __align__(16) __half g_wo[64*136];      // out1 weights fp16, [n][k] stride 136

// ---------------- helpers ----------------
__device__ __forceinline__ void mma16(float c[4], const uint32_t a[4], const uint32_t b[2]) {
    asm volatile(
        "mma.sync.aligned.m16n8k16.row.col.f32.f16.f16.f32 "
        "{%0,%1,%2,%3},{%4,%5,%6,%7},{%8,%9},{%0,%1,%2,%3};\n"
        : "+f"(c[0]), "+f"(c[1]), "+f"(c[2]), "+f"(c[3])
        : "r"(a[0]), "r"(a[1]), "r"(a[2]), "r"(a[3]), "r"(b[0]), "r"(b[1]));
}

// ---------------- weight prep ----------------
// blocks 0-5: gconv [k][n] fp32 -> [n][k] fp16 stride 136
// block 6:    out1  [k][64] fp32 -> [n][k] fp16 stride 136
__global__ void wprep_kernel(const float* __restrict__ lw, const float* __restrict__ nw,
                             const float* __restrict__ ow) {
    int bidx = blockIdx.x;
    if (bidx < 6) {
        int m = bidx & 1, l = bidx >> 1;
        const float* src = (m ? nw : lw) + l * 16384;
        __half* dst = g_wh + bidx * (128 * 136);
        for (int idx = threadIdx.x; idx < 16384; idx += 256) {
            int k = idx >> 7, n = idx & 127;
            dst[n * 136 + k] = __float2half_rn(src[idx]);
        }
    } else {
        for (int idx = threadIdx.x; idx < 8192; idx += 256) {
            int k = idx >> 6, n = idx & 63;
            g_wo[n * 136 + k] = __float2half_rn(ow[k * 64 + n]);
        }
    }
}

// ---------------- gconv: persistent multi-tile, fp16 HMMA, 2 CTA/SM ----------------
// smem bytes: Ah [66][136]h @0 (17952) | A2h [64][136]h @17952 (17408)
//             WLh @35360 (34816) | WNh @70176 (34816) | stats @104992 (3584)
// epilogue S fp32 [64][132] reuses @0
#define GCONV_SMEM 108576

__global__ __launch_bounds__(256, 2) void gconv_kernel(
    const __half* __restrict__ wimg,
    const float* __restrict__ lb, const float* __restrict__ nbb,
    const float* __restrict__ mask,
    const float* __restrict__ xin, const float* __restrict__ ew, const float* __restrict__ ebias,
    const float* __restrict__ hin, const float* __restrict__ gin,
    float* __restrict__ hout, float* __restrict__ gout, int mode)   // 2 = emb layer0, 1 = fused BN
{
    extern __shared__ char smc[];
    __half* Ah  = (__half*)smc;               // logical row lr at smem row lr+1
    __half* A2h = (__half*)(smc + 17952);
    __half* WLh = (__half*)(smc + 35360);
    __half* WNh = (__half*)(smc + 70176);
    float* ssum = (float*)(smc + 104992);
    float* ssq  = ssum + 128;
    float* scs  = ssq + 128;
    float* shs  = scs + 128;
    float* ew0  = shs + 128;
    float* ew1  = ew0 + 128;
    float* ebb  = ew1 + 128;
    float* S    = (float*)smc;                // epilogue reuse [64][132]

    const int tid = threadIdx.x;
    const int bid = blockIdx.x;

    if (tid < 128) {
        ssum[tid] = 0.f; ssq[tid] = 0.f;
        scs[tid] = g_sc[tid]; shs[tid] = g_sh[tid];
        ew0[tid] = ew[tid]; ew1[tid] = ew[128 + tid]; ebb[tid] = ebias[tid];
    }
    // weights: once per persistent CTA
    {
        const uint4* wl4 = (const uint4*)wimg;
        const uint4* wn4 = (const uint4*)(wimg + 128 * 136);
        uint4* WL4 = (uint4*)WLh;
        uint4* WN4 = (uint4*)WNh;
        for (int i = tid; i < 2176; i += 256) {
            WL4[i] = wl4[i];
            WN4[i] = wn4[i];
        }
    }

    const int w = tid >> 5, lane = tid & 31;
    const int g = lane >> 2, t4 = lane & 3;
    const int wm = w & 1, wn = w >> 1;        // 2 m x 4 n warp grid
    const bool isR = (wn >= 2);
    const int rbase = wm * 32;
    const int cb = (wn & 1) * 64;
    const uint32_t* AU  = (const uint32_t*)(isR ? A2h : Ah);
    const uint32_t* WU  = (const uint32_t*)(isR ? WNh : WLh);
    const int rowadd = isR ? 0 : 68;

    for (int t = bid; t < NTILES; t += GGRID) {
        const int b = t >> 7;
        const int n_base = (t & 127) << 6;
        const size_t tok0 = (size_t)b * NBATCH + n_base;

        __syncthreads();   // S/Ah reuse from previous tile done

        // A tile with halo (66 rows)
        for (int idx = tid; idx < 66 * 32; idx += 256) {
            int r = idx >> 5, c4 = (idx & 31) << 2;
            int lr = r - 1;
            int n = (n_base + lr) & (NBATCH - 1);
            size_t tok = (size_t)b * NBATCH + n;
            float4 v;
            if (mode == 2) {
                float x0 = xin[tok * 2], x1 = xin[tok * 2 + 1];
                v.x = x0 * ew0[c4]     + x1 * ew1[c4]     + ebb[c4];
                v.y = x0 * ew0[c4 + 1] + x1 * ew1[c4 + 1] + ebb[c4 + 1];
                v.z = x0 * ew0[c4 + 2] + x1 * ew1[c4 + 2] + ebb[c4 + 2];
                v.w = x0 * ew0[c4 + 3] + x1 * ew1[c4 + 3] + ebb[c4 + 3];
                if (lr >= 0 && lr < 64) *(float4*)(hout + tok * HD + c4) = v;
            } else {
                size_t goff = tok * HD + c4;
                v = *(const float4*)(hin + goff);
                float4 gv = *(const float4*)(gin + goff);
                v.x += fmaxf(0.f, gv.x * scs[c4]     + shs[c4]);
                v.y += fmaxf(0.f, gv.y * scs[c4 + 1] + shs[c4 + 1]);
                v.z += fmaxf(0.f, gv.z * scs[c4 + 2] + shs[c4 + 2]);
                v.w += fmaxf(0.f, gv.w * scs[c4 + 3] + shs[c4 + 3]);
                if (lr >= 0 && lr < 64) *(float4*)(hout + goff) = v;
            }
            __half2 p0 = __floats2half2_rn(v.x, v.y);
            __half2 p1 = __floats2half2_rn(v.z, v.w);
            uint2 pk;
            pk.x = *(uint32_t*)&p0; pk.y = *(uint32_t*)&p1;
            *(uint2*)(Ah + r * 136 + c4) = pk;
        }
        __syncthreads();
        // A2 = neighbor sum
        {
            const uint32_t* AUl = (const uint32_t*)Ah;
            uint32_t* A2U = (uint32_t*)A2h;
            for (int idx = tid; idx < 64 * 64; idx += 256) {
                int r = idx >> 6, j = idx & 63;
                uint32_t lo = AUl[r * 68 + j];
                uint32_t hi = AUl[(r + 2) * 68 + j];
                float2 flo = __half22float2(*(__half2*)&lo);
                float2 fhi = __half22float2(*(__half2*)&hi);
                __half2 sres = __floats2half2_rn(flo.x + fhi.x, flo.y + fhi.y);
                A2U[r * 68 + j] = *(uint32_t*)&sres;
            }
        }
        __syncthreads();

        float acc[2][8][4];
        #pragma unroll
        for (int i = 0; i < 2; i++)
            #pragma unroll
            for (int j = 0; j < 8; j++)
                #pragma unroll
                for (int q = 0; q < 4; q++) acc[i][j][q] = 0.f;

        #pragma unroll
        for (int ks = 0; ks < 8; ks++) {
            const int k2 = ks * 8;
            uint32_t afr[2][4];
            #pragma unroll
            for (int mt = 0; mt < 2; mt++) {
                const uint32_t* p = AU + (rbase + mt * 16 + g) * 68 + rowadd + k2 + t4;
                afr[mt][0] = p[0];
                afr[mt][1] = p[8 * 68];
                afr[mt][2] = p[4];
                afr[mt][3] = p[8 * 68 + 4];
            }
            uint32_t bfr[8][2];
            #pragma unroll
            for (int nt = 0; nt < 8; nt++) {
                const uint32_t* p = WU + (cb + nt * 8 + g) * 68 + k2 + t4;
                bfr[nt][0] = p[0];
                bfr[nt][1] = p[4];
            }
            #pragma unroll
            for (int mt = 0; mt < 2; mt++)
                #pragma unroll
                for (int nt = 0; nt < 8; nt++)
                    mma16(acc[mt][nt], afr[mt], bfr[nt]);
        }

        __syncthreads();     // fp16 A reads done; S may overwrite

        if (isR) {
            #pragma unroll
            for (int mt = 0; mt < 2; mt++)
                #pragma unroll
                for (int nt = 0; nt < 8; nt++) {
                    int r = rbase + mt * 16 + g;
                    int c = cb + nt * 8 + t4 * 2;
                    S[r * 132 + c]           = acc[mt][nt][0];
                    S[r * 132 + c + 1]       = acc[mt][nt][1];
                    S[(r + 8) * 132 + c]     = acc[mt][nt][2];
                    S[(r + 8) * 132 + c + 1] = acc[mt][nt][3];
                }
        }
        __syncthreads();
        if (!isR) {
            #pragma unroll
            for (int mt = 0; mt < 2; mt++) {
                int r = rbase + mt * 16 + g;
                float m0 = mask[tok0 + r];
                float m1 = mask[tok0 + r + 8];
                #pragma unroll
                for (int nt = 0; nt < 8; nt++) {
                    int c = cb + nt * 8 + t4 * 2;
                    float bia0 = lb[c] + nbb[c];
                    float bia1 = lb[c + 1] + nbb[c + 1];
                    S[r * 132 + c]           = (acc[mt][nt][0] + S[r * 132 + c]           + bia0) * m0;
                    S[r * 132 + c + 1]       = (acc[mt][nt][1] + S[r * 132 + c + 1]       + bia1) * m0;
                    S[(r + 8) * 132 + c]     = (acc[mt][nt][2] + S[(r + 8) * 132 + c]     + bia0) * m1;
                    S[(r + 8) * 132 + c + 1] = (acc[mt][nt][3] + S[(r + 8) * 132 + c + 1] + bia1) * m1;
                }
            }
        }
        __syncthreads();

        {
            int c = tid & 127, seg = tid >> 7;
            float s = 0.f, q = 0.f;
            #pragma unroll 8
            for (int r = seg * 32; r < seg * 32 + 32; r++) {
                float v = S[r * 132 + c];
                s += v; q += v * v;
            }
            atomicAdd(&ssum[c], s);
            atomicAdd(&ssq[c], q);
        }
        for (int idx = tid; idx < 64 * 32; idx += 256) {
            int r = idx >> 5, c4 = (idx & 31) << 2;
            float4 v = *(const float4*)(S + r * 132 + c4);
            *(float4*)(gout + (tok0 + r) * HD + c4) = v;
        }
    }
    __syncthreads();
    if (tid < 256) g_part[bid * 256 + tid] = (tid < 128) ? ssum[tid] : ssq[tid - 128];
}

// ---------------- BN reduce (GGRID partials) ----------------
__global__ void bnreduce_kernel(const float* __restrict__ gam, const float* __restrict__ bet) {
    __shared__ float rs[256], rq[256];
    int c = blockIdx.x, tid = threadIdx.x;
    float s = 0.f, q = 0.f;
    for (int i = tid; i < GGRID; i += 256) {
        s += g_part[i * 256 + c];
        q += g_part[i * 256 + 128 + c];
    }
    rs[tid] = s; rq[tid] = q;
    __syncthreads();
    for (int o = 128; o > 0; o >>= 1) {
        if (tid < o) { rs[tid] += rs[tid + o]; rq[tid] += rq[tid + o]; }
        __syncthreads();
    }
    if (tid == 0) {
        float inv = 1.f / (float)TOK;
        float mean = rs[0] * inv;
        float var = rq[0] * inv - mean * mean;
        float sc = gam[c] * rsqrtf(var + 1e-5f);
        g_sc[c] = sc;
        g_sh[c] = bet[c] - mean * sc;
    }
}

// ---------------- output head: persistent, fp16 HMMA, fused final BN ----------------
// smem bytes: Ah [64][136]h @0 (17408) | W1h [64][136]h @17408 (17408)
//             S fp32 [64][72] @34816 (18432) | W2s @53248 (512) | B1s @53760 (256)
//             scs @54016 (512) | shs @54528 (512)
#define OUT_SMEM 55040

__global__ __launch_bounds__(256, 2) void out_kernel(
    const float* __restrict__ b1,
    const float* __restrict__ w2, const float* __restrict__ b2,
    const float* __restrict__ mask, float* __restrict__ out,
    const float* __restrict__ hin, const float* __restrict__ gin)
{
    extern __shared__ char smc[];
    __half* Ah  = (__half*)smc;
    __half* W1h = (__half*)(smc + 17408);
    float* S    = (float*)(smc + 34816);   // [64][72]
    float* W2s  = (float*)(smc + 53248);
    float* B1s  = (float*)(smc + 53760);
    float* scs  = (float*)(smc + 54016);
    float* shs  = (float*)(smc + 54528);

    const int tid = threadIdx.x, bid = blockIdx.x;

    if (tid < 128) { scs[tid] = g_sc[tid]; shs[tid] = g_sh[tid]; W2s[tid] = w2[tid]; }
    if (tid < 64)  B1s[tid] = b1[tid];
    {
        const uint4* wsrc = (const uint4*)g_wo;
        uint4* wdst = (uint4*)W1h;
        for (int i = tid; i < 1088; i += 256) wdst[i] = wsrc[i];
    }

    const int w = tid >> 5, lane = tid & 31;
    const int g = lane >> 2, t4 = lane & 3;
    const int wm = w & 1, wn = w >> 1;      // 2 m x 4 n (16 cols each)
    const int rbase = wm * 32;
    const int cbN = wn * 16;
    const uint32_t* AU  = (const uint32_t*)Ah;
    const uint32_t* WU  = (const uint32_t*)W1h;
    const float b2v[2] = { b2[0], b2[1] };

    for (int t = bid; t < NTILES; t += GGRID) {
        const size_t tok0 = (size_t)t * 64;

        __syncthreads();   // previous tile's S reads / Ah reads done

        // A = h2 + relu(bn2(G2)), fp16
        for (int idx = tid; idx < 64 * 32; idx += 256) {
            int r = idx >> 5, c4 = (idx & 31) << 2;
            size_t goff = (tok0 + r) * HD + c4;
            float4 hv = *(const float4*)(hin + goff);
            float4 gv = *(const float4*)(gin + goff);
            hv.x += fmaxf(0.f, gv.x * scs[c4]     + shs[c4]);
            hv.y += fmaxf(0.f, gv.y * scs[c4 + 1] + shs[c4 + 1]);
            hv.z += fmaxf(0.f, gv.z * scs[c4 + 2] + shs[c4 + 2]);
            hv.w += fmaxf(0.f, gv.w * scs[c4 + 3] + shs[c4 + 3]);
            __half2 p0 = __floats2half2_rn(hv.x, hv.y);
            __half2 p1 = __floats2half2_rn(hv.z, hv.w);
            uint2 pk;
            pk.x = *(uint32_t*)&p0; pk.y = *(uint32_t*)&p1;
            *(uint2*)(Ah + r * 136 + c4) = pk;
        }
        __syncthreads();

        float acc[2][2][4];
        #pragma unroll
        for (int i = 0; i < 2; i++)
            #pragma unroll
            for (int j = 0; j < 2; j++)
                #pragma unroll
                for (int q = 0; q < 4; q++) acc[i][j][q] = 0.f;

        #pragma unroll
        for (int ks = 0; ks < 8; ks++) {
            const int k2 = ks * 8;
            uint32_t afr[2][4];
            #pragma unroll
            for (int mt = 0; mt < 2; mt++) {
                const uint32_t* p = AU + (rbase + mt * 16 + g) * 68 + k2 + t4;
                afr[mt][0] = p[0];
                afr[mt][1] = p[8 * 68];
                afr[mt][2] = p[4];
                afr[mt][3] = p[8 * 68 + 4];
            }
            uint32_t bfr[2][2];
            #pragma unroll
            for (int nt = 0; nt < 2; nt++) {
                const uint32_t* p = WU + (cbN + nt * 8 + g) * 68 + k2 + t4;
                bfr[nt][0] = p[0];
                bfr[nt][1] = p[4];
            }
            #pragma unroll
            for (int mt = 0; mt < 2; mt++)
                #pragma unroll
                for (int nt = 0; nt < 2; nt++)
                    mma16(acc[mt][nt], afr[mt], bfr[nt]);
        }

        // S = relu(acc + b1), [64][72]
        #pragma unroll
        for (int mt = 0; mt < 2; mt++)
            #pragma unroll
            for (int nt = 0; nt < 2; nt++) {
                int r = rbase + mt * 16 + g;
                int c = cbN + nt * 8 + t4 * 2;
                S[r * 72 + c]           = fmaxf(0.f, acc[mt][nt][0] + B1s[c]);
                S[r * 72 + c + 1]       = fmaxf(0.f, acc[mt][nt][1] + B1s[c + 1]);
                S[(r + 8) * 72 + c]     = fmaxf(0.f, acc[mt][nt][2] + B1s[c]);
                S[(r + 8) * 72 + c + 1] = fmaxf(0.f, acc[mt][nt][3] + B1s[c + 1]);
            }
        __syncthreads();

        if (tid < 128) {
            int r = tid >> 1, o = tid & 1;
            float s = 0.f;
            #pragma unroll
            for (int j = 0; j < 64; j++) s += S[r * 72 + j] * W2s[j * 2 + o];
            out[(tok0 + r) * 2 + o] = (s + b2v[o]) * mask[tok0 + r];
        }
    }
}

// ---------------- launch ----------------
extern "C" void kernel_launch(void* const* d_in, const int* in_sizes, int n_in,
                              void* d_out, int out_size) {
    const float* x     = (const float*)d_in[0];
    const float* mask  = (const float*)d_in[1];
    const float* emb_w = (const float*)d_in[2];
    const float* emb_b = (const float*)d_in[3];
    const float* lin_w = (const float*)d_in[4];
    const float* lin_b = (const float*)d_in[5];
    const float* nb_w  = (const float*)d_in[6];
    const float* nb_b  = (const float*)d_in[7];
    const float* bn_g  = (const float*)d_in[8];
    const float* bn_b  = (const float*)d_in[9];
    const float* o1w   = (const float*)d_in[10];
    const float* o1b   = (const float*)d_in[11];
    const float* o2w   = (const float*)d_in[12];
    const float* o2b   = (const float*)d_in[13];
    float* out = (float*)d_out;

    float *hA, *hB, *gP, *gQ;
    __half* wh;
    cudaGetSymbolAddress((void**)&hA, g_h);
    cudaGetSymbolAddress((void**)&hB, g_h2);
    cudaGetSymbolAddress((void**)&gP, g_gP);
    cudaGetSymbolAddress((void**)&gQ, g_gQ);
    cudaGetSymbolAddress((void**)&wh, g_wh);

    cudaFuncSetAttribute(gconv_kernel, cudaFuncAttributeMaxDynamicSharedMemorySize, GCONV_SMEM);
    cudaFuncSetAttribute(out_kernel,   cudaFuncAttributeMaxDynamicSharedMemorySize, OUT_SMEM);

    const int WSTR = 128 * 136;

    wprep_kernel<<<7, 256>>>(lin_w, nb_w, o1w);          // my launch 1 (global 3)
    // layer 0 (emb fused): A=emb(x); h0 -> hA, G0 -> gP    (global 4)
    gconv_kernel<<<GGRID, 256, GCONV_SMEM>>>(wh + 0 * WSTR, lin_b, nb_b, mask,
                                             x, emb_w, emb_b, hA, hA, hA, gP, 2);
    bnreduce_kernel<<<128, 256>>>(bn_g, bn_b);           // (global 5)
    // layer 1 — global slot 6, ncu lands here (fuse=1 heavy variant)
    gconv_kernel<<<GGRID, 256, GCONV_SMEM>>>(wh + 2 * WSTR, lin_b + 128, nb_b + 128, mask,
                                             x, emb_w, emb_b, hA, gP, hB, gQ, 1);
    bnreduce_kernel<<<128, 256>>>(bn_g + 128, bn_b + 128);
    gconv_kernel<<<GGRID, 256, GCONV_SMEM>>>(wh + 4 * WSTR, lin_b + 256, nb_b + 256, mask,
                                             x, emb_w, emb_b, hB, gQ, hA, gP, 1);
    bnreduce_kernel<<<128, 256>>>(bn_g + 256, bn_b + 256);
    out_kernel<<<GGRID, 256, OUT_SMEM>>>(o1b, o2w, o2b, mask, out, hA, gP);
}

// round 10
// speedup vs baseline: 2.2384x; 1.2200x over previous
#include <cuda_runtime.h>
#include <cuda_fp16.h>
#include <cstdint>

#define TOK (32*8192)
#define NBATCH 8192
#define HD 128
#define GGRID 304
#define NTILES 4096

// ---------------- scratch ----------------
__device__ __align__(16) float  g_h [(size_t)TOK*HD];
__device__ __align__(16) float  g_h2[(size_t)TOK*HD];
__device__ __align__(16) __half g_gPh[(size_t)TOK*HD];   // pre-BN G, fp16
__device__ __align__(16) __half g_gQh[(size_t)TOK*HD];
__device__ __align__(16) float g_part[GGRID*256];
__device__ float g_sc[128];
__device__ float g_sh[128];
__device__ __align__(16) __half g_wh[6*128*136];   // gconv weights fp16, [n][k] stride 136
__device__ __align__(16) __half g_wo[64*136];      // out1 weights fp16, [n][k] stride 136

// ---------------- helpers ----------------
__device__ __forceinline__ void mma16(float c[4], const uint32_t a[4], const uint32_t b[2]) {
    asm volatile(
        "mma.sync.aligned.m16n8k16.row.col.f32.f16.f16.f32 "
        "{%0,%1,%2,%3},{%4,%5,%6,%7},{%8,%9},{%0,%1,%2,%3};\n"
        : "+f"(c[0]), "+f"(c[1]), "+f"(c[2]), "+f"(c[3])
        : "r"(a[0]), "r"(a[1]), "r"(a[2]), "r"(a[3]), "r"(b[0]), "r"(b[1]));
}
__device__ __forceinline__ uint32_t hadd2u(uint32_t a, uint32_t b) {
    __half2 r = __hadd2(*(__half2*)&a, *(__half2*)&b);
    return *(uint32_t*)&r;
}

// ---------------- weight prep ----------------
__global__ void wprep_kernel(const float* __restrict__ lw, const float* __restrict__ nw,
                             const float* __restrict__ ow) {
    int bidx = blockIdx.x;
    if (bidx < 6) {
        int m = bidx & 1, l = bidx >> 1;
        const float* src = (m ? nw : lw) + l * 16384;
        __half* dst = g_wh + bidx * (128 * 136);
        for (int idx = threadIdx.x; idx < 16384; idx += 256) {
            int k = idx >> 7, n = idx & 127;
            dst[n * 136 + k] = __float2half_rn(src[idx]);
        }
    } else {
        for (int idx = threadIdx.x; idx < 8192; idx += 256) {
            int k = idx >> 6, n = idx & 63;
            g_wo[n * 136 + k] = __float2half_rn(ow[k * 64 + n]);
        }
    }
}

// ---------------- gconv: persistent, combined-acc fp16 HMMA, fp16 G ----------------
// smem bytes: Ah [66][136]h @0 (17952) | WLh @17952 (34816) | WNh @52768 (34816)
//             stats @87584 (4096)  -> total 91680
// epilogue S fp16 [64][136] reuses Ah region
#define GCONV_SMEM 91680

__global__ __launch_bounds__(256, 2) void gconv_kernel(
    const __half* __restrict__ wimg,
    const float* __restrict__ lb, const float* __restrict__ nbb,
    const float* __restrict__ mask,
    const float* __restrict__ xin, const float* __restrict__ ew, const float* __restrict__ ebias,
    const float* __restrict__ hin, const __half* __restrict__ gin,
    float* __restrict__ hout, __half* __restrict__ gout, int mode)  // 2 = emb layer0, 1 = fused BN
{
    extern __shared__ char smc[];
    __half* Ah  = (__half*)smc;               // logical row lr at smem row lr+1, stride 136
    __half* WLh = (__half*)(smc + 17952);
    __half* WNh = (__half*)(smc + 52768);
    float* ssum = (float*)(smc + 87584);
    float* ssq  = ssum + 128;
    float* scs  = ssq + 128;
    float* shs  = scs + 128;
    float* ew0  = shs + 128;
    float* ew1  = ew0 + 128;
    float* ebb  = ew1 + 128;
    float* bbv  = ebb + 128;
    __half* S   = (__half*)smc;               // epilogue reuse, [64][136]

    const int tid = threadIdx.x;
    const int bid = blockIdx.x;

    if (tid < 128) {
        ssum[tid] = 0.f; ssq[tid] = 0.f;
        scs[tid] = g_sc[tid]; shs[tid] = g_sh[tid];
        ew0[tid] = ew[tid]; ew1[tid] = ew[128 + tid]; ebb[tid] = ebias[tid];
        bbv[tid] = lb[tid] + nbb[tid];
    }
    {
        const uint4* wl4 = (const uint4*)wimg;
        const uint4* wn4 = (const uint4*)(wimg + 128 * 136);
        uint4* WL4 = (uint4*)WLh;
        uint4* WN4 = (uint4*)WNh;
        for (int i = tid; i < 2176; i += 256) {
            WL4[i] = wl4[i];
            WN4[i] = wn4[i];
        }
    }

    const int w = tid >> 5, lane = tid & 31;
    const int g = lane >> 2, t4 = lane & 3;
    const int wm = w & 1, wn = w >> 1;        // 2 m x 4 n warp grid (32 cols per warp)
    const int rbase = wm * 32;
    const int cbN = wn * 32;
    const uint32_t* AhU = (const uint32_t*)Ah;   // stride 68 u32 per smem row
    const uint32_t* WLU = (const uint32_t*)WLh;
    const uint32_t* WNU = (const uint32_t*)WNh;
    uint32_t* SU = (uint32_t*)S;

    for (int t = bid; t < NTILES; t += GGRID) {
        const int b = t >> 7;
        const int n_base = (t & 127) << 6;
        const size_t tok0 = (size_t)b * NBATCH + n_base;

        __syncthreads();   // prev tile's S reads done; Ah reusable

        // ---- load A tile with halo (66 rows) ----
        for (int idx = tid; idx < 66 * 32; idx += 256) {
            int r = idx >> 5, c4 = (idx & 31) << 2;
            int lr = r - 1;
            int n = (n_base + lr) & (NBATCH - 1);
            size_t tok = (size_t)b * NBATCH + n;
            float4 v;
            if (mode == 2) {
                float x0 = xin[tok * 2], x1 = xin[tok * 2 + 1];
                v.x = x0 * ew0[c4]     + x1 * ew1[c4]     + ebb[c4];
                v.y = x0 * ew0[c4 + 1] + x1 * ew1[c4 + 1] + ebb[c4 + 1];
                v.z = x0 * ew0[c4 + 2] + x1 * ew1[c4 + 2] + ebb[c4 + 2];
                v.w = x0 * ew0[c4 + 3] + x1 * ew1[c4 + 3] + ebb[c4 + 3];
                if (lr >= 0 && lr < 64) *(float4*)(hout + tok * HD + c4) = v;
            } else {
                size_t goff = tok * HD + c4;
                v = *(const float4*)(hin + goff);
                uint2 gp = *(const uint2*)(gin + goff);
                float2 g0 = __half22float2(*(__half2*)&gp.x);
                float2 g1 = __half22float2(*(__half2*)&gp.y);
                v.x += fmaxf(0.f, g0.x * scs[c4]     + shs[c4]);
                v.y += fmaxf(0.f, g0.y * scs[c4 + 1] + shs[c4 + 1]);
                v.z += fmaxf(0.f, g1.x * scs[c4 + 2] + shs[c4 + 2]);
                v.w += fmaxf(0.f, g1.y * scs[c4 + 3] + shs[c4 + 3]);
                if (lr >= 0 && lr < 64) *(float4*)(hout + goff) = v;
            }
            __half2 p0 = __floats2half2_rn(v.x, v.y);
            __half2 p1 = __floats2half2_rn(v.z, v.w);
            uint2 pk;
            pk.x = *(uint32_t*)&p0; pk.y = *(uint32_t*)&p1;
            *(uint2*)(Ah + r * 136 + c4) = pk;
        }
        __syncthreads();

        // ---- mainloop: acc = A@WL + A2@WN, A2 fragments built inline ----
        float acc[2][4][4];
        #pragma unroll
        for (int i = 0; i < 2; i++)
            #pragma unroll
            for (int j = 0; j < 4; j++)
                #pragma unroll
                for (int q = 0; q < 4; q++) acc[i][j][q] = 0.f;

        #pragma unroll
        for (int ks = 0; ks < 8; ks++) {
            const int k2 = ks * 8;
            uint32_t afr[2][4], a2fr[2][4];
            #pragma unroll
            for (int mt = 0; mt < 2; mt++) {
                int lr = rbase + mt * 16 + g;           // logical row
                const uint32_t* pc = AhU + (lr + 1) * 68 + k2 + t4;   // center
                afr[mt][0] = pc[0];
                afr[mt][1] = pc[8 * 68];
                afr[mt][2] = pc[4];
                afr[mt][3] = pc[8 * 68 + 4];
                const uint32_t* pl = AhU + lr * 68 + k2 + t4;         // logical lr-1
                const uint32_t* ph = AhU + (lr + 2) * 68 + k2 + t4;   // logical lr+1
                a2fr[mt][0] = hadd2u(pl[0],          ph[0]);
                a2fr[mt][1] = hadd2u(pl[8 * 68],     ph[8 * 68]);
                a2fr[mt][2] = hadd2u(pl[4],          ph[4]);
                a2fr[mt][3] = hadd2u(pl[8 * 68 + 4], ph[8 * 68 + 4]);
            }
            uint32_t bL[4][2], bN[4][2];
            #pragma unroll
            for (int nt = 0; nt < 4; nt++) {
                const uint32_t* pL = WLU + (cbN + nt * 8 + g) * 68 + k2 + t4;
                const uint32_t* pN = WNU + (cbN + nt * 8 + g) * 68 + k2 + t4;
                bL[nt][0] = pL[0]; bL[nt][1] = pL[4];
                bN[nt][0] = pN[0]; bN[nt][1] = pN[4];
            }
            #pragma unroll
            for (int mt = 0; mt < 2; mt++)
                #pragma unroll
                for (int nt = 0; nt < 4; nt++) {
                    mma16(acc[mt][nt], afr[mt],  bL[nt]);
                    mma16(acc[mt][nt], a2fr[mt], bN[nt]);
                }
        }

        __syncthreads();     // all Ah reads done; S (same region) may be written

        // ---- epilogue: bias + mask -> S fp16 ----
        #pragma unroll
        for (int mt = 0; mt < 2; mt++) {
            int r = rbase + mt * 16 + g;
            float m0 = mask[tok0 + r];
            float m1 = mask[tok0 + r + 8];
            #pragma unroll
            for (int nt = 0; nt < 4; nt++) {
                int c = cbN + nt * 8 + t4 * 2;
                float b0 = bbv[c], b1 = bbv[c + 1];
                __half2 v0 = __floats2half2_rn((acc[mt][nt][0] + b0) * m0, (acc[mt][nt][1] + b1) * m0);
                __half2 v1 = __floats2half2_rn((acc[mt][nt][2] + b0) * m1, (acc[mt][nt][3] + b1) * m1);
                SU[r * 68 + (c >> 1)]       = *(uint32_t*)&v0;
                SU[(r + 8) * 68 + (c >> 1)] = *(uint32_t*)&v1;
            }
        }
        __syncthreads();

        // ---- stats from fp16 S (consistent with stored G) + store G ----
        {
            int c = tid & 127, seg = tid >> 7;
            float s = 0.f, q = 0.f;
            #pragma unroll 8
            for (int r = seg * 32; r < seg * 32 + 32; r++) {
                float v = __half2float(S[r * 136 + c]);
                s += v; q += v * v;
            }
            atomicAdd(&ssum[c], s);
            atomicAdd(&ssq[c], q);
        }
        for (int idx = tid; idx < 1024; idx += 256) {
            int r = idx >> 4, qw = idx & 15;
            uint4 v = *(const uint4*)(SU + r * 68 + qw * 4);
            *(uint4*)(gout + (tok0 + r) * HD + qw * 8) = v;
        }
    }
    __syncthreads();
    if (tid < 256) g_part[bid * 256 + tid] = (tid < 128) ? ssum[tid] : ssq[tid - 128];
}

// ---------------- BN reduce ----------------
__global__ void bnreduce_kernel(const float* __restrict__ gam, const float* __restrict__ bet) {
    __shared__ float rs[256], rq[256];
    int c = blockIdx.x, tid = threadIdx.x;
    float s = 0.f, q = 0.f;
    for (int i = tid; i < GGRID; i += 256) {
        s += g_part[i * 256 + c];
        q += g_part[i * 256 + 128 + c];
    }
    rs[tid] = s; rq[tid] = q;
    __syncthreads();
    for (int o = 128; o > 0; o >>= 1) {
        if (tid < o) { rs[tid] += rs[tid + o]; rq[tid] += rq[tid + o]; }
        __syncthreads();
    }
    if (tid == 0) {
        float inv = 1.f / (float)TOK;
        float mean = rs[0] * inv;
        float var = rq[0] * inv - mean * mean;
        float sc = gam[c] * rsqrtf(var + 1e-5f);
        g_sc[c] = sc;
        g_sh[c] = bet[c] - mean * sc;
    }
}

// ---------------- output head: persistent, fp16 HMMA, fp16 G in ----------------
#define OUT_SMEM 55040

__global__ __launch_bounds__(256, 2) void out_kernel(
    const float* __restrict__ b1,
    const float* __restrict__ w2, const float* __restrict__ b2,
    const float* __restrict__ mask, float* __restrict__ out,
    const float* __restrict__ hin, const __half* __restrict__ gin)
{
    extern __shared__ char smc[];
    __half* Ah  = (__half*)smc;
    __half* W1h = (__half*)(smc + 17408);
    float* S    = (float*)(smc + 34816);   // [64][72]
    float* W2s  = (float*)(smc + 53248);
    float* B1s  = (float*)(smc + 53760);
    float* scs  = (float*)(smc + 54016);
    float* shs  = (float*)(smc + 54528);

    const int tid = threadIdx.x, bid = blockIdx.x;

    if (tid < 128) { scs[tid] = g_sc[tid]; shs[tid] = g_sh[tid]; W2s[tid] = w2[tid]; }
    if (tid < 64)  B1s[tid] = b1[tid];
    {
        const uint4* wsrc = (const uint4*)g_wo;
        uint4* wdst = (uint4*)W1h;
        for (int i = tid; i < 1088; i += 256) wdst[i] = wsrc[i];
    }

    const int w = tid >> 5, lane = tid & 31;
    const int g = lane >> 2, t4 = lane & 3;
    const int wm = w & 1, wn = w >> 1;
    const int rbase = wm * 32;
    const int cbN = wn * 16;
    const uint32_t* AU = (const uint32_t*)Ah;
    const uint32_t* WU = (const uint32_t*)W1h;
    const float b2v[2] = { b2[0], b2[1] };

    for (int t = bid; t < NTILES; t += GGRID) {
        const size_t tok0 = (size_t)t * 64;

        __syncthreads();

        for (int idx = tid; idx < 64 * 32; idx += 256) {
            int r = idx >> 5, c4 = (idx & 31) << 2;
            size_t goff = (tok0 + r) * HD + c4;
            float4 hv = *(const float4*)(hin + goff);
            uint2 gp = *(const uint2*)(gin + goff);
            float2 g0 = __half22float2(*(__half2*)&gp.x);
            float2 g1 = __half22float2(*(__half2*)&gp.y);
            hv.x += fmaxf(0.f, g0.x * scs[c4]     + shs[c4]);
            hv.y += fmaxf(0.f, g0.y * scs[c4 + 1] + shs[c4 + 1]);
            hv.z += fmaxf(0.f, g1.x * scs[c4 + 2] + shs[c4 + 2]);
            hv.w += fmaxf(0.f, g1.y * scs[c4 + 3] + shs[c4 + 3]);
            __half2 p0 = __floats2half2_rn(hv.x, hv.y);
            __half2 p1 = __floats2half2_rn(hv.z, hv.w);
            uint2 pk;
            pk.x = *(uint32_t*)&p0; pk.y = *(uint32_t*)&p1;
            *(uint2*)(Ah + r * 136 + c4) = pk;
        }
        __syncthreads();

        float acc[2][2][4];
        #pragma unroll
        for (int i = 0; i < 2; i++)
            #pragma unroll
            for (int j = 0; j < 2; j++)
                #pragma unroll
                for (int q = 0; q < 4; q++) acc[i][j][q] = 0.f;

        #pragma unroll
        for (int ks = 0; ks < 8; ks++) {
            const int k2 = ks * 8;
            uint32_t afr[2][4];
            #pragma unroll
            for (int mt = 0; mt < 2; mt++) {
                const uint32_t* p = AU + (rbase + mt * 16 + g) * 68 + k2 + t4;
                afr[mt][0] = p[0];
                afr[mt][1] = p[8 * 68];
                afr[mt][2] = p[4];
                afr[mt][3] = p[8 * 68 + 4];
            }
            uint32_t bfr[2][2];
            #pragma unroll
            for (int nt = 0; nt < 2; nt++) {
                const uint32_t* p = WU + (cbN + nt * 8 + g) * 68 + k2 + t4;
                bfr[nt][0] = p[0];
                bfr[nt][1] = p[4];
            }
            #pragma unroll
            for (int mt = 0; mt < 2; mt++)
                #pragma unroll
                for (int nt = 0; nt < 2; nt++)
                    mma16(acc[mt][nt], afr[mt], bfr[nt]);
        }

        #pragma unroll
        for (int mt = 0; mt < 2; mt++)
            #pragma unroll
            for (int nt = 0; nt < 2; nt++) {
                int r = rbase + mt * 16 + g;
                int c = cbN + nt * 8 + t4 * 2;
                S[r * 72 + c]           = fmaxf(0.f, acc[mt][nt][0] + B1s[c]);
                S[r * 72 + c + 1]       = fmaxf(0.f, acc[mt][nt][1] + B1s[c + 1]);
                S[(r + 8) * 72 + c]     = fmaxf(0.f, acc[mt][nt][2] + B1s[c]);
                S[(r + 8) * 72 + c + 1] = fmaxf(0.f, acc[mt][nt][3] + B1s[c + 1]);
            }
        __syncthreads();

        if (tid < 128) {
            int r = tid >> 1, o = tid & 1;
            float s = 0.f;
            #pragma unroll
            for (int j = 0; j < 64; j++) s += S[r * 72 + j] * W2s[j * 2 + o];
            out[(tok0 + r) * 2 + o] = (s + b2v[o]) * mask[tok0 + r];
        }
    }
}

// ---------------- launch ----------------
extern "C" void kernel_launch(void* const* d_in, const int* in_sizes, int n_in,
                              void* d_out, int out_size) {
    const float* x     = (const float*)d_in[0];
    const float* mask  = (const float*)d_in[1];
    const float* emb_w = (const float*)d_in[2];
    const float* emb_b = (const float*)d_in[3];
    const float* lin_w = (const float*)d_in[4];
    const float* lin_b = (const float*)d_in[5];
    const float* nb_w  = (const float*)d_in[6];
    const float* nb_b  = (const float*)d_in[7];
    const float* bn_g  = (const float*)d_in[8];
    const float* bn_b  = (const float*)d_in[9];
    const float* o1w   = (const float*)d_in[10];
    const float* o1b   = (const float*)d_in[11];
    const float* o2w   = (const float*)d_in[12];
    const float* o2b   = (const float*)d_in[13];
    float* out = (float*)d_out;

    float *hA, *hB;
    __half *gPh, *gQh, *wh;
    cudaGetSymbolAddress((void**)&hA, g_h);
    cudaGetSymbolAddress((void**)&hB, g_h2);
    cudaGetSymbolAddress((void**)&gPh, g_gPh);
    cudaGetSymbolAddress((void**)&gQh, g_gQh);
    cudaGetSymbolAddress((void**)&wh, g_wh);

    cudaFuncSetAttribute(gconv_kernel, cudaFuncAttributeMaxDynamicSharedMemorySize, GCONV_SMEM);
    cudaFuncSetAttribute(out_kernel,   cudaFuncAttributeMaxDynamicSharedMemorySize, OUT_SMEM);

    const int WSTR = 128 * 136;

    wprep_kernel<<<7, 256>>>(lin_w, nb_w, o1w);
    // layer 0 (emb fused): h0 -> hA, G0 -> gPh
    gconv_kernel<<<GGRID, 256, GCONV_SMEM>>>(wh + 0 * WSTR, lin_b, nb_b, mask,
                                             x, emb_w, emb_b, hA, gPh, hA, gPh, 2);
    bnreduce_kernel<<<128, 256>>>(bn_g, bn_b);
    // layer 1 — profile slot 6 (fuse=1 heavy variant)
    gconv_kernel<<<GGRID, 256, GCONV_SMEM>>>(wh + 2 * WSTR, lin_b + 128, nb_b + 128, mask,
                                             x, emb_w, emb_b, hA, gPh, hB, gQh, 1);
    bnreduce_kernel<<<128, 256>>>(bn_g + 128, bn_b + 128);
    gconv_kernel<<<GGRID, 256, GCONV_SMEM>>>(wh + 4 * WSTR, lin_b + 256, nb_b + 256, mask,
                                             x, emb_w, emb_b, hB, gQh, hA, gPh, 1);
    bnreduce_kernel<<<128, 256>>>(bn_g + 256, bn_b + 256);
    out_kernel<<<GGRID, 256, OUT_SMEM>>>(o1b, o2w, o2b, mask, out, hA, gPh);
}

// round 11
// speedup vs baseline: 2.6938x; 1.2035x over previous
#include <cuda_runtime.h>
#include <cuda_fp16.h>
#include <cstdint>

#define TOK (32*8192)
#define NBATCH 8192
#define HD 128
#define GGRID 304
#define NTILES 4096

// ---------------- scratch ----------------
__device__ __align__(16) float  g_h [(size_t)TOK*HD];
__device__ __align__(16) float  g_h2[(size_t)TOK*HD];
__device__ __align__(16) __half g_gPh[(size_t)TOK*HD];
__device__ __align__(16) __half g_gQh[(size_t)TOK*HD];
__device__ __align__(16) float g_part[GGRID*256];
__device__ float g_sc[128];
__device__ float g_sh[128];
__device__ unsigned g_ctr;
__device__ __align__(16) __half g_wh[6*128*136];
__device__ __align__(16) __half g_wo[64*136];

// ---------------- helpers ----------------
__device__ __forceinline__ void mma16(float c[4], const uint32_t a[4], const uint32_t b[2]) {
    asm volatile(
        "mma.sync.aligned.m16n8k16.row.col.f32.f16.f16.f32 "
        "{%0,%1,%2,%3},{%4,%5,%6,%7},{%8,%9},{%0,%1,%2,%3};\n"
        : "+f"(c[0]), "+f"(c[1]), "+f"(c[2]), "+f"(c[3])
        : "r"(a[0]), "r"(a[1]), "r"(a[2]), "r"(a[3]), "r"(b[0]), "r"(b[1]));
}
__device__ __forceinline__ uint32_t hadd2u(uint32_t a, uint32_t b) {
    __half2 r = __hadd2(*(__half2*)&a, *(__half2*)&b);
    return *(uint32_t*)&r;
}

// ---------------- weight prep ----------------
__global__ void wprep_kernel(const float* __restrict__ lw, const float* __restrict__ nw,
                             const float* __restrict__ ow) {
    int bidx = blockIdx.x;
    if (bidx < 6) {
        int m = bidx & 1, l = bidx >> 1;
        const float* src = (m ? nw : lw) + l * 16384;
        __half* dst = g_wh + bidx * (128 * 136);
        for (int idx = threadIdx.x; idx < 16384; idx += 256) {
            int k = idx >> 7, n = idx & 127;
            dst[n * 136 + k] = __float2half_rn(src[idx]);
        }
    } else {
        for (int idx = threadIdx.x; idx < 8192; idx += 256) {
            int k = idx >> 6, n = idx & 63;
            g_wo[n * 136 + k] = __float2half_rn(ow[k * 64 + n]);
        }
    }
}

// ---------------- gconv: persistent, combined-acc fp16 HMMA, batched loads, fused BN reduce ----------------
// smem bytes: Ah [66][136]h @0 (17952) | WLh @17952 (34816) | WNh @52768 (34816)
//             stats @87584 (4112) -> total 91696
#define GCONV_SMEM 91696

__global__ __launch_bounds__(256, 2) void gconv_kernel(
    const __half* __restrict__ wimg,
    const float* __restrict__ lb, const float* __restrict__ nbb,
    const float* __restrict__ gam, const float* __restrict__ bet,
    const float* __restrict__ mask,
    const float* __restrict__ xin, const float* __restrict__ ew, const float* __restrict__ ebias,
    const float* __restrict__ hin, const __half* __restrict__ gin,
    float* __restrict__ hout, __half* __restrict__ gout, int mode)  // 2 = emb layer0, 1 = fused BN
{
    extern __shared__ char smc[];
    __half* Ah  = (__half*)smc;               // logical row lr at smem row lr+1, stride 136
    __half* WLh = (__half*)(smc + 17952);
    __half* WNh = (__half*)(smc + 52768);
    float* ssum = (float*)(smc + 87584);
    float* ssq  = ssum + 128;
    float* scs  = ssq + 128;
    float* shs  = scs + 128;
    float* ew0  = shs + 128;
    float* ew1  = ew0 + 128;
    float* ebb  = ew1 + 128;
    float* bbv  = ebb + 128;
    float* redflag = bbv + 128;
    __half* S   = (__half*)smc;               // epilogue reuse, [64][136]

    const int tid = threadIdx.x;
    const int bid = blockIdx.x;

    if (tid < 128) {
        ssum[tid] = 0.f; ssq[tid] = 0.f;
        scs[tid] = g_sc[tid]; shs[tid] = g_sh[tid];
        ew0[tid] = ew[tid]; ew1[tid] = ew[128 + tid]; ebb[tid] = ebias[tid];
        bbv[tid] = lb[tid] + nbb[tid];
    }
    {
        const uint4* wl4 = (const uint4*)wimg;
        const uint4* wn4 = (const uint4*)(wimg + 128 * 136);
        uint4* WL4 = (uint4*)WLh;
        uint4* WN4 = (uint4*)WNh;
        for (int i = tid; i < 2176; i += 256) {
            WL4[i] = wl4[i];
            WN4[i] = wn4[i];
        }
    }

    const int w = tid >> 5, lane = tid & 31;
    const int g = lane >> 2, t4 = lane & 3;
    const int wm = w & 1, wn = w >> 1;
    const int rbase = wm * 32;
    const int cbN = wn * 32;
    const uint32_t* AhU = (const uint32_t*)Ah;
    const uint32_t* WLU = (const uint32_t*)WLh;
    const uint32_t* WNU = (const uint32_t*)WNh;
    uint32_t* SU = (uint32_t*)S;

    const int lr0 = tid >> 5;                 // row group 0..7
    const int c4  = (tid & 31) << 2;          // fixed channel group

    for (int t = bid; t < NTILES; t += GGRID) {
        const int b = t >> 7;
        const int n_base = (t & 127) << 6;
        const size_t tok0 = (size_t)b * NBATCH + n_base;

        __syncthreads();   // prev tile's S reads done; Ah reusable

        // ---- batched A-tile load (8 exact iters + 64-thread halo) ----
        const size_t gbase = (tok0 + lr0) * HD + c4;
        const int nH = (tid < 32) ? ((n_base - 1) & (NBATCH - 1)) : ((n_base + 64) & (NBATCH - 1));
        const size_t tokH = (size_t)b * NBATCH + nH;

        if (mode == 1) {
            float4 vh[9]; uint2 vg[9];
            #pragma unroll
            for (int i = 0; i < 8; i++) {
                size_t go = gbase + (size_t)(8 * i) * HD;
                vh[i] = *(const float4*)(hin + go);
                vg[i] = *(const uint2*)(gin + go);
            }
            if (tid < 64) {
                size_t goH = tokH * HD + c4;
                vh[8] = *(const float4*)(hin + goH);
                vg[8] = *(const uint2*)(gin + goH);
            }
            #pragma unroll
            for (int i = 0; i < 8; i++) {
                float4 v = vh[i];
                float2 g0 = __half22float2(*(__half2*)&vg[i].x);
                float2 g1 = __half22float2(*(__half2*)&vg[i].y);
                v.x += fmaxf(0.f, g0.x * scs[c4]     + shs[c4]);
                v.y += fmaxf(0.f, g0.y * scs[c4 + 1] + shs[c4 + 1]);
                v.z += fmaxf(0.f, g1.x * scs[c4 + 2] + shs[c4 + 2]);
                v.w += fmaxf(0.f, g1.y * scs[c4 + 3] + shs[c4 + 3]);
                *(float4*)(hout + gbase + (size_t)(8 * i) * HD) = v;
                __half2 p0 = __floats2half2_rn(v.x, v.y);
                __half2 p1 = __floats2half2_rn(v.z, v.w);
                uint2 pk; pk.x = *(uint32_t*)&p0; pk.y = *(uint32_t*)&p1;
                *(uint2*)(Ah + (1 + lr0 + 8 * i) * 136 + c4) = pk;
            }
            if (tid < 64) {
                float4 v = vh[8];
                float2 g0 = __half22float2(*(__half2*)&vg[8].x);
                float2 g1 = __half22float2(*(__half2*)&vg[8].y);
                v.x += fmaxf(0.f, g0.x * scs[c4]     + shs[c4]);
                v.y += fmaxf(0.f, g0.y * scs[c4 + 1] + shs[c4 + 1]);
                v.z += fmaxf(0.f, g1.x * scs[c4 + 2] + shs[c4 + 2]);
                v.w += fmaxf(0.f, g1.y * scs[c4 + 3] + shs[c4 + 3]);
                __half2 p0 = __floats2half2_rn(v.x, v.y);
                __half2 p1 = __floats2half2_rn(v.z, v.w);
                uint2 pk; pk.x = *(uint32_t*)&p0; pk.y = *(uint32_t*)&p1;
                int rH = (tid < 32) ? 0 : 65;
                *(uint2*)(Ah + rH * 136 + c4) = pk;
            }
        } else {
            float2 xv[9];
            #pragma unroll
            for (int i = 0; i < 8; i++)
                xv[i] = *(const float2*)(xin + (tok0 + lr0 + 8 * i) * 2);
            if (tid < 64) xv[8] = *(const float2*)(xin + tokH * 2);
            #pragma unroll
            for (int i = 0; i < 8; i++) {
                float x0 = xv[i].x, x1 = xv[i].y;
                float4 v;
                v.x = x0 * ew0[c4]     + x1 * ew1[c4]     + ebb[c4];
                v.y = x0 * ew0[c4 + 1] + x1 * ew1[c4 + 1] + ebb[c4 + 1];
                v.z = x0 * ew0[c4 + 2] + x1 * ew1[c4 + 2] + ebb[c4 + 2];
                v.w = x0 * ew0[c4 + 3] + x1 * ew1[c4 + 3] + ebb[c4 + 3];
                *(float4*)(hout + gbase + (size_t)(8 * i) * HD) = v;
                __half2 p0 = __floats2half2_rn(v.x, v.y);
                __half2 p1 = __floats2half2_rn(v.z, v.w);
                uint2 pk; pk.x = *(uint32_t*)&p0; pk.y = *(uint32_t*)&p1;
                *(uint2*)(Ah + (1 + lr0 + 8 * i) * 136 + c4) = pk;
            }
            if (tid < 64) {
                float x0 = xv[8].x, x1 = xv[8].y;
                float4 v;
                v.x = x0 * ew0[c4]     + x1 * ew1[c4]     + ebb[c4];
                v.y = x0 * ew0[c4 + 1] + x1 * ew1[c4 + 1] + ebb[c4 + 1];
                v.z = x0 * ew0[c4 + 2] + x1 * ew1[c4 + 2] + ebb[c4 + 2];
                v.w = x0 * ew0[c4 + 3] + x1 * ew1[c4 + 3] + ebb[c4 + 3];
                __half2 p0 = __floats2half2_rn(v.x, v.y);
                __half2 p1 = __floats2half2_rn(v.z, v.w);
                uint2 pk; pk.x = *(uint32_t*)&p0; pk.y = *(uint32_t*)&p1;
                int rH = (tid < 32) ? 0 : 65;
                *(uint2*)(Ah + rH * 136 + c4) = pk;
            }
        }
        __syncthreads();

        // ---- mainloop: acc = A@WL + A2@WN ----
        float acc[2][4][4];
        #pragma unroll
        for (int i = 0; i < 2; i++)
            #pragma unroll
            for (int j = 0; j < 4; j++)
                #pragma unroll
                for (int q = 0; q < 4; q++) acc[i][j][q] = 0.f;

        #pragma unroll
        for (int ks = 0; ks < 8; ks++) {
            const int k2 = ks * 8;
            uint32_t afr[2][4], a2fr[2][4];
            #pragma unroll
            for (int mt = 0; mt < 2; mt++) {
                int lr = rbase + mt * 16 + g;
                const uint32_t* pc = AhU + (lr + 1) * 68 + k2 + t4;
                afr[mt][0] = pc[0];
                afr[mt][1] = pc[8 * 68];
                afr[mt][2] = pc[4];
                afr[mt][3] = pc[8 * 68 + 4];
                const uint32_t* pl = AhU + lr * 68 + k2 + t4;
                const uint32_t* ph = AhU + (lr + 2) * 68 + k2 + t4;
                a2fr[mt][0] = hadd2u(pl[0],          ph[0]);
                a2fr[mt][1] = hadd2u(pl[8 * 68],     ph[8 * 68]);
                a2fr[mt][2] = hadd2u(pl[4],          ph[4]);
                a2fr[mt][3] = hadd2u(pl[8 * 68 + 4], ph[8 * 68 + 4]);
            }
            uint32_t bL[4][2], bN[4][2];
            #pragma unroll
            for (int nt = 0; nt < 4; nt++) {
                const uint32_t* pL = WLU + (cbN + nt * 8 + g) * 68 + k2 + t4;
                const uint32_t* pN = WNU + (cbN + nt * 8 + g) * 68 + k2 + t4;
                bL[nt][0] = pL[0]; bL[nt][1] = pL[4];
                bN[nt][0] = pN[0]; bN[nt][1] = pN[4];
            }
            #pragma unroll
            for (int mt = 0; mt < 2; mt++)
                #pragma unroll
                for (int nt = 0; nt < 4; nt++) {
                    mma16(acc[mt][nt], afr[mt],  bL[nt]);
                    mma16(acc[mt][nt], a2fr[mt], bN[nt]);
                }
        }

        __syncthreads();

        // ---- epilogue: bias + mask -> S fp16 ----
        #pragma unroll
        for (int mt = 0; mt < 2; mt++) {
            int r = rbase + mt * 16 + g;
            float m0 = mask[tok0 + r];
            float m1 = mask[tok0 + r + 8];
            #pragma unroll
            for (int nt = 0; nt < 4; nt++) {
                int c = cbN + nt * 8 + t4 * 2;
                float b0 = bbv[c], b1 = bbv[c + 1];
                __half2 v0 = __floats2half2_rn((acc[mt][nt][0] + b0) * m0, (acc[mt][nt][1] + b1) * m0);
                __half2 v1 = __floats2half2_rn((acc[mt][nt][2] + b0) * m1, (acc[mt][nt][3] + b1) * m1);
                SU[r * 68 + (c >> 1)]       = *(uint32_t*)&v0;
                SU[(r + 8) * 68 + (c >> 1)] = *(uint32_t*)&v1;
            }
        }
        __syncthreads();

        // ---- stats + store G ----
        {
            int c = tid & 127, seg = tid >> 7;
            float s = 0.f, q = 0.f;
            #pragma unroll 8
            for (int r = seg * 32; r < seg * 32 + 32; r++) {
                float v = __half2float(S[r * 136 + c]);
                s += v; q += v * v;
            }
            atomicAdd(&ssum[c], s);
            atomicAdd(&ssq[c], q);
        }
        for (int idx = tid; idx < 1024; idx += 256) {
            int r = idx >> 4, qw = idx & 15;
            uint4 v = *(const uint4*)(SU + r * 68 + qw * 4);
            *(uint4*)(gout + (tok0 + r) * HD + qw * 8) = v;
        }
    }
    __syncthreads();
    if (tid < 256) g_part[bid * 256 + tid] = (tid < 128) ? ssum[tid] : ssq[tid - 128];

    // ---- last-CTA BN reduce (threadFenceReduction pattern) ----
    __threadfence();
    __syncthreads();
    if (tid == 0) {
        unsigned old = atomicAdd(&g_ctr, 1u);
        redflag[0] = (old == GGRID - 1) ? 1.f : 0.f;
    }
    __syncthreads();
    if (redflag[0] != 0.f) {
        int c = tid & 127, seg = tid >> 7;   // 2 segs x 152 CTAs
        float s = 0.f, q = 0.f;
        for (int i = seg * 152; i < seg * 152 + 152; i++) {
            s += g_part[i * 256 + c];
            q += g_part[i * 256 + 128 + c];
        }
        if (seg == 0) { ssum[c] = s; ssq[c] = q; }
        __syncthreads();
        if (seg == 1) {
            float S2 = ssum[c] + s, Q2 = ssq[c] + q;
            float inv = 1.f / (float)TOK;
            float mean = S2 * inv;
            float var = Q2 * inv - mean * mean;
            float sc = gam[c] * rsqrtf(var + 1e-5f);
            g_sc[c] = sc;
            g_sh[c] = bet[c] - mean * sc;
        }
        if (tid == 0) g_ctr = 0;
    }
}

// ---------------- output head: persistent, fp16 HMMA, batched loads ----------------
#define OUT_SMEM 55040

__global__ __launch_bounds__(256, 2) void out_kernel(
    const float* __restrict__ b1,
    const float* __restrict__ w2, const float* __restrict__ b2,
    const float* __restrict__ mask, float* __restrict__ out,
    const float* __restrict__ hin, const __half* __restrict__ gin)
{
    extern __shared__ char smc[];
    __half* Ah  = (__half*)smc;
    __half* W1h = (__half*)(smc + 17408);
    float* S    = (float*)(smc + 34816);
    float* W2s  = (float*)(smc + 53248);
    float* B1s  = (float*)(smc + 53760);
    float* scs  = (float*)(smc + 54016);
    float* shs  = (float*)(smc + 54528);

    const int tid = threadIdx.x, bid = blockIdx.x;

    if (tid < 128) { scs[tid] = g_sc[tid]; shs[tid] = g_sh[tid]; W2s[tid] = w2[tid]; }
    if (tid < 64)  B1s[tid] = b1[tid];
    {
        const uint4* wsrc = (const uint4*)g_wo;
        uint4* wdst = (uint4*)W1h;
        for (int i = tid; i < 1088; i += 256) wdst[i] = wsrc[i];
    }

    const int w = tid >> 5, lane = tid & 31;
    const int g = lane >> 2, t4 = lane & 3;
    const int wm = w & 1, wn = w >> 1;
    const int rbase = wm * 32;
    const int cbN = wn * 16;
    const uint32_t* AU = (const uint32_t*)Ah;
    const uint32_t* WU = (const uint32_t*)W1h;
    const float b2v[2] = { b2[0], b2[1] };

    const int lr0 = tid >> 5;
    const int c4  = (tid & 31) << 2;

    for (int t = bid; t < NTILES; t += GGRID) {
        const size_t tok0 = (size_t)t * 64;

        __syncthreads();

        const size_t gbase = (tok0 + lr0) * HD + c4;
        float4 vh[8]; uint2 vg[8];
        #pragma unroll
        for (int i = 0; i < 8; i++) {
            size_t go = gbase + (size_t)(8 * i) * HD;
            vh[i] = *(const float4*)(hin + go);
            vg[i] = *(const uint2*)(gin + go);
        }
        #pragma unroll
        for (int i = 0; i < 8; i++) {
            float4 hv = vh[i];
            float2 g0 = __half22float2(*(__half2*)&vg[i].x);
            float2 g1 = __half22float2(*(__half2*)&vg[i].y);
            hv.x += fmaxf(0.f, g0.x * scs[c4]     + shs[c4]);
            hv.y += fmaxf(0.f, g0.y * scs[c4 + 1] + shs[c4 + 1]);
            hv.z += fmaxf(0.f, g1.x * scs[c4 + 2] + shs[c4 + 2]);
            hv.w += fmaxf(0.f, g1.y * scs[c4 + 3] + shs[c4 + 3]);
            __half2 p0 = __floats2half2_rn(hv.x, hv.y);
            __half2 p1 = __floats2half2_rn(hv.z, hv.w);
            uint2 pk; pk.x = *(uint32_t*)&p0; pk.y = *(uint32_t*)&p1;
            *(uint2*)(Ah + (lr0 + 8 * i) * 136 + c4) = pk;
        }
        __syncthreads();

        float acc[2][2][4];
        #pragma unroll
        for (int i = 0; i < 2; i++)
            #pragma unroll
            for (int j = 0; j < 2; j++)
                #pragma unroll
                for (int q = 0; q < 4; q++) acc[i][j][q] = 0.f;

        #pragma unroll
        for (int ks = 0; ks < 8; ks++) {
            const int k2 = ks * 8;
            uint32_t afr[2][4];
            #pragma unroll
            for (int mt = 0; mt < 2; mt++) {
                const uint32_t* p = AU + (rbase + mt * 16 + g) * 68 + k2 + t4;
                afr[mt][0] = p[0];
                afr[mt][1] = p[8 * 68];
                afr[mt][2] = p[4];
                afr[mt][3] = p[8 * 68 + 4];
            }
            uint32_t bfr[2][2];
            #pragma unroll
            for (int nt = 0; nt < 2; nt++) {
                const uint32_t* p = WU + (cbN + nt * 8 + g) * 68 + k2 + t4;
                bfr[nt][0] = p[0];
                bfr[nt][1] = p[4];
            }
            #pragma unroll
            for (int mt = 0; mt < 2; mt++)
                #pragma unroll
                for (int nt = 0; nt < 2; nt++)
                    mma16(acc[mt][nt], afr[mt], bfr[nt]);
        }

        #pragma unroll
        for (int mt = 0; mt < 2; mt++)
            #pragma unroll
            for (int nt = 0; nt < 2; nt++) {
                int r = rbase + mt * 16 + g;
                int c = cbN + nt * 8 + t4 * 2;
                S[r * 72 + c]           = fmaxf(0.f, acc[mt][nt][0] + B1s[c]);
                S[r * 72 + c + 1]       = fmaxf(0.f, acc[mt][nt][1] + B1s[c + 1]);
                S[(r + 8) * 72 + c]     = fmaxf(0.f, acc[mt][nt][2] + B1s[c]);
                S[(r + 8) * 72 + c + 1] = fmaxf(0.f, acc[mt][nt][3] + B1s[c + 1]);
            }
        __syncthreads();

        if (tid < 128) {
            int r = tid >> 1, o = tid & 1;
            float s = 0.f;
            #pragma unroll
            for (int j = 0; j < 64; j++) s += S[r * 72 + j] * W2s[j * 2 + o];
            out[(tok0 + r) * 2 + o] = (s + b2v[o]) * mask[tok0 + r];
        }
    }
}

// ---------------- launch ----------------
extern "C" void kernel_launch(void* const* d_in, const int* in_sizes, int n_in,
                              void* d_out, int out_size) {
    const float* x     = (const float*)d_in[0];
    const float* mask  = (const float*)d_in[1];
    const float* emb_w = (const float*)d_in[2];
    const float* emb_b = (const float*)d_in[3];
    const float* lin_w = (const float*)d_in[4];
    const float* lin_b = (const float*)d_in[5];
    const float* nb_w  = (const float*)d_in[6];
    const float* nb_b  = (const float*)d_in[7];
    const float* bn_g  = (const float*)d_in[8];
    const float* bn_b  = (const float*)d_in[9];
    const float* o1w   = (const float*)d_in[10];
    const float* o1b   = (const float*)d_in[11];
    const float* o2w   = (const float*)d_in[12];
    const float* o2b   = (const float*)d_in[13];
    float* out = (float*)d_out;

    float *hA, *hB;
    __half *gPh, *gQh, *wh;
    cudaGetSymbolAddress((void**)&hA, g_h);
    cudaGetSymbolAddress((void**)&hB, g_h2);
    cudaGetSymbolAddress((void**)&gPh, g_gPh);
    cudaGetSymbolAddress((void**)&gQh, g_gQh);
    cudaGetSymbolAddress((void**)&wh, g_wh);

    cudaFuncSetAttribute(gconv_kernel, cudaFuncAttributeMaxDynamicSharedMemorySize, GCONV_SMEM);
    cudaFuncSetAttribute(out_kernel,   cudaFuncAttributeMaxDynamicSharedMemorySize, OUT_SMEM);

    const int WSTR = 128 * 136;

    wprep_kernel<<<7, 256>>>(lin_w, nb_w, o1w);
    // layer 0 (emb fused): h0 -> hA, G0 -> gPh; BN0 reduced in-kernel
    gconv_kernel<<<GGRID, 256, GCONV_SMEM>>>(wh + 0 * WSTR, lin_b, nb_b,
                                             bn_g, bn_b, mask,
                                             x, emb_w, emb_b, hA, gPh, hA, gPh, 2);
    gconv_kernel<<<GGRID, 256, GCONV_SMEM>>>(wh + 2 * WSTR, lin_b + 128, nb_b + 128,
                                             bn_g + 128, bn_b + 128, mask,
                                             x, emb_w, emb_b, hA, gPh, hB, gQh, 1);
    gconv_kernel<<<GGRID, 256, GCONV_SMEM>>>(wh + 4 * WSTR, lin_b + 256, nb_b + 256,
                                             bn_g + 256, bn_b + 256, mask,
                                             x, emb_w, emb_b, hB, gQh, hA, gPh, 1);
    out_kernel<<<GGRID, 256, OUT_SMEM>>>(o1b, o2w, o2b, mask, out, hA, gPh);
}